// round 1
// baseline (speedup 1.0000x reference)
#include <cuda_runtime.h>
#include <math.h>

// B=1024, D=512, N=16, H=512, M = N*B = 16384
#define DD   512
#define NN   16
#define HH   512
#define MTOT 16384

// Scratch (static __device__ — no allocations allowed)
__device__ float g_S1[MTOT * DD];   // lrelu(xT @ Ws1 + bs1)
__device__ float g_Sh[MTOT * DD];   // shared = lrelu(S1 @ Ws2 + bs2), layout [b][n][d]

__device__ __forceinline__ float lrelu(float v) { return v >= 0.f ? v : 0.1f * v; }

// ---------------------------------------------------------------------------
// Generic 128x128x16-tile SGEMM with lrelu(+bias) epilogue.
// MODE 0: A[r,k] = x[b, k, n] with r = b*16+n (transpose-gather of x (B,D,N)),
//         writes g_S1.
// MODE 1: A = g_S1 row-major, writes g_Sh.
// ---------------------------------------------------------------------------
template <int MODE>
__global__ __launch_bounds__(256)
void gemm_lrelu_kernel(const float* __restrict__ Ain,
                       const float* __restrict__ W,
                       const float* __restrict__ bias)
{
    __shared__ float As[16][128];   // [k][m]
    __shared__ float Ws[16][128];   // [k][n]

    const int tid  = threadIdx.x;          // 256 threads
    const int g    = tid >> 4;             // 0..15  (row group)
    const int c    = tid & 15;             // 0..15  (col group)
    const int row0 = blockIdx.x * 128;
    const int col0 = blockIdx.y * 128;

    float acc[8][8];
    #pragma unroll
    for (int i = 0; i < 8; i++)
        #pragma unroll
        for (int j = 0; j < 8; j++) acc[i][j] = 0.f;

    const float* A = (MODE == 0) ? Ain : g_S1;
    float*       C = (MODE == 0) ? g_S1 : g_Sh;

    for (int k0 = 0; k0 < DD; k0 += 16) {
        // --- load A tile (128 rows x 16 k) ---
        if (MODE == 0) {
            #pragma unroll
            for (int i = 0; i < 8; i++) {
                int e = tid + i * 256;
                int r = e >> 4, k = e & 15;
                int gr = row0 + r;
                int b  = gr >> 4, nn = gr & 15;        // r = b*16 + n
                As[k][r] = A[(size_t)b * (DD * NN) + (size_t)(k0 + k) * NN + nn];
            }
        } else {
            #pragma unroll
            for (int i = 0; i < 2; i++) {
                int f = tid + i * 256;
                int r = f >> 2, c4 = f & 3;
                float4 v = *reinterpret_cast<const float4*>(
                    &A[(size_t)(row0 + r) * DD + k0 + c4 * 4]);
                As[c4 * 4 + 0][r] = v.x;
                As[c4 * 4 + 1][r] = v.y;
                As[c4 * 4 + 2][r] = v.z;
                As[c4 * 4 + 3][r] = v.w;
            }
        }
        // --- load W tile (16 k x 128 cols), row-major ld=512 ---
        #pragma unroll
        for (int i = 0; i < 2; i++) {
            int f = tid + i * 256;
            int k = f >> 5, c4 = f & 31;
            *reinterpret_cast<float4*>(&Ws[k][c4 * 4]) =
                *reinterpret_cast<const float4*>(
                    &W[(size_t)(k0 + k) * DD + col0 + c4 * 4]);
        }
        __syncthreads();

        #pragma unroll
        for (int k = 0; k < 16; k++) {
            float a[8], b[8];
            #pragma unroll
            for (int q = 0; q < 4; q++) {
                a[q]     = As[k][g * 4 + q];
                a[4 + q] = As[k][64 + g * 4 + q];
                b[q]     = Ws[k][c * 4 + q];
                b[4 + q] = Ws[k][64 + c * 4 + q];
            }
            #pragma unroll
            for (int i = 0; i < 8; i++)
                #pragma unroll
                for (int j = 0; j < 8; j++) acc[i][j] += a[i] * b[j];
        }
        __syncthreads();
    }

    // --- epilogue: bias + lrelu, float4 stores ---
    #pragma unroll
    for (int i = 0; i < 8; i++) {
        int r = row0 + ((i < 4) ? g * 4 + i : 64 + g * 4 + (i - 4));
        #pragma unroll
        for (int jj = 0; jj < 2; jj++) {
            int cb = col0 + ((jj == 0) ? c * 4 : 64 + c * 4);
            float4 v;
            v.x = lrelu(acc[i][jj * 4 + 0] + bias[cb + 0]);
            v.y = lrelu(acc[i][jj * 4 + 1] + bias[cb + 1]);
            v.z = lrelu(acc[i][jj * 4 + 2] + bias[cb + 2]);
            v.w = lrelu(acc[i][jj * 4 + 3] + bias[cb + 3]);
            *reinterpret_cast<float4*>(&C[(size_t)r * DD + cb]) = v;
        }
    }
}

// ---------------------------------------------------------------------------
// Fused classifier GEMM: for head n, h-block, m-tile:
//   acc = full_in[m,:] @ Wc1[n,:,h0:h0+128]        (K=512)
//   partial[m] = sum_h lrelu(acc + bc1[n,h]) * Wc2[n,h]
//   atomicAdd into logits (= d_out full_out region, m*16+n)
// full_in row m = shared[b=m%1024, n'=m/1024, :]  -> g_Sh row (m%1024)*16 + m/1024
// ---------------------------------------------------------------------------
__global__ __launch_bounds__(256)
void gemm_head_kernel(const float* __restrict__ Wc1,
                      const float* __restrict__ bc1,
                      const float* __restrict__ Wc2,
                      float* __restrict__ logits)
{
    __shared__ float As[16][128];
    __shared__ float Ws[16][128];

    const int tid  = threadIdx.x;
    const int g    = tid >> 4;
    const int c    = tid & 15;
    const int row0 = blockIdx.x * 128;
    const int h0   = blockIdx.y * 128;
    const int n    = blockIdx.z;
    const float* W = Wc1 + (size_t)n * DD * HH;

    float acc[8][8];
    #pragma unroll
    for (int i = 0; i < 8; i++)
        #pragma unroll
        for (int j = 0; j < 8; j++) acc[i][j] = 0.f;

    for (int k0 = 0; k0 < DD; k0 += 16) {
        #pragma unroll
        for (int i = 0; i < 2; i++) {
            int f = tid + i * 256;
            int r = f >> 2, c4 = f & 3;
            int m = row0 + r;
            int srow = (m & 1023) * 16 + (m >> 10);
            float4 v = *reinterpret_cast<const float4*>(
                &g_Sh[(size_t)srow * DD + k0 + c4 * 4]);
            As[c4 * 4 + 0][r] = v.x;
            As[c4 * 4 + 1][r] = v.y;
            As[c4 * 4 + 2][r] = v.z;
            As[c4 * 4 + 3][r] = v.w;
        }
        #pragma unroll
        for (int i = 0; i < 2; i++) {
            int f = tid + i * 256;
            int k = f >> 5, c4 = f & 31;
            *reinterpret_cast<float4*>(&Ws[k][c4 * 4]) =
                *reinterpret_cast<const float4*>(
                    &W[(size_t)(k0 + k) * HH + h0 + c4 * 4]);
        }
        __syncthreads();

        #pragma unroll
        for (int k = 0; k < 16; k++) {
            float a[8], b[8];
            #pragma unroll
            for (int q = 0; q < 4; q++) {
                a[q]     = As[k][g * 4 + q];
                a[4 + q] = As[k][64 + g * 4 + q];
                b[q]     = Ws[k][c * 4 + q];
                b[4 + q] = Ws[k][64 + c * 4 + q];
            }
            #pragma unroll
            for (int i = 0; i < 8; i++)
                #pragma unroll
                for (int j = 0; j < 8; j++) acc[i][j] += a[i] * b[j];
        }
        __syncthreads();
    }

    // fused epilogue: lrelu(+bc1), weight by Wc2, reduce over h, atomic into logits
    float p[8];
    #pragma unroll
    for (int i = 0; i < 8; i++) p[i] = 0.f;

    #pragma unroll
    for (int j = 0; j < 8; j++) {
        int h = h0 + ((j < 4) ? c * 4 + j : 64 + c * 4 + (j - 4));
        float b1 = bc1[n * HH + h];
        float w2 = Wc2[n * HH + h];
        #pragma unroll
        for (int i = 0; i < 8; i++) {
            float v = lrelu(acc[i][j] + b1);
            p[i] += v * w2;
        }
    }

    #pragma unroll
    for (int i = 0; i < 8; i++) {
        float v = p[i];
        // reduce across the 16 col-group lanes (lane bits 0..3 within the warp)
        v += __shfl_xor_sync(0xffffffffu, v, 1);
        v += __shfl_xor_sync(0xffffffffu, v, 2);
        v += __shfl_xor_sync(0xffffffffu, v, 4);
        v += __shfl_xor_sync(0xffffffffu, v, 8);
        if (c == 0) {
            int r = row0 + ((i < 4) ? g * 4 + i : 64 + g * 4 + (i - 4));
            atomicAdd(&logits[r * NN + n], v);
        }
    }
}

__global__ void zero_kernel(float* __restrict__ p, int n)
{
    int i = blockIdx.x * 256 + threadIdx.x;
    if (i < n) p[i] = 0.f;
}

// full_out += bc2; out[b,n] = sigmoid(diagonal of full_out)
__global__ void finalize_kernel(float* __restrict__ out,
                                const float* __restrict__ bc2)
{
    int idx = blockIdx.x * 256 + threadIdx.x;      // < 262144
    int m = idx >> 4, n = idx & 15;
    float* full = out + MTOT;                       // full_out region
    float v = full[idx] + bc2[n];
    full[idx] = v;
    if ((m >> 10) == n) {                           // m = n*1024 + b  -> diagonal
        int b = m & 1023;
        out[b * NN + n] = 1.f / (1.f + expf(-v));
    }
}

extern "C" void kernel_launch(void* const* d_in, const int* in_sizes, int n_in,
                              void* d_out, int out_size)
{
    const float* x   = (const float*)d_in[0];
    const float* Ws1 = (const float*)d_in[1];
    const float* bs1 = (const float*)d_in[2];
    const float* Ws2 = (const float*)d_in[3];
    const float* bs2 = (const float*)d_in[4];
    const float* Wc1 = (const float*)d_in[5];
    const float* bc1 = (const float*)d_in[6];
    const float* Wc2 = (const float*)d_in[7];
    const float* bc2 = (const float*)d_in[8];
    float* out = (float*)d_out;

    dim3 blk(256);
    // GEMM1: S1 = lrelu(xT @ Ws1 + bs1)
    gemm_lrelu_kernel<0><<<dim3(MTOT / 128, DD / 128), blk>>>(x, Ws1, bs1);
    // GEMM2: shared = lrelu(S1 @ Ws2 + bs2)
    gemm_lrelu_kernel<1><<<dim3(MTOT / 128, DD / 128), blk>>>(nullptr, Ws2, bs2);
    // zero the full_out accumulation region (d_out + 16384, 262144 floats)
    zero_kernel<<<(MTOT * NN + 255) / 256, blk>>>(out + MTOT, MTOT * NN);
    // GEMM3 fused classifier: 128 m-tiles x 4 h-blocks x 16 heads
    gemm_head_kernel<<<dim3(MTOT / 128, HH / 128, NN), blk>>>(Wc1, bc1, Wc2, out + MTOT);
    // bias + sigmoid diagonal extraction
    finalize_kernel<<<(MTOT * NN + 255) / 256, blk>>>(out, bc2);
}

// round 3
// speedup vs baseline: 2.1054x; 2.1054x over previous
#include <cuda_runtime.h>
#include <math.h>
#include <stdint.h>

// B=1024, D=512, N=16, H=512, M = N*B = 16384
#define DD   512
#define NN   16
#define HH   512
#define MTOT 16384

// Scratch (static __device__ — no allocations allowed)
__device__ float g_S1[MTOT * DD];   // lrelu(xT @ Ws1 + bs1), rows r = b*16+n
__device__ float g_Sh[MTOT * DD];   // shared, PERMUTED rows: m = n*1024 + b

__device__ __forceinline__ float lrelu(float v) { return v >= 0.f ? v : 0.1f * v; }

__device__ __forceinline__ uint32_t f2tf32(float f) {
    uint32_t u;
    asm("cvt.rna.tf32.f32 %0, %1;" : "=r"(u) : "f"(f));
    return u;
}

__device__ __forceinline__ void mma8(float* c, const uint32_t* a, const uint32_t* b) {
    asm volatile(
        "mma.sync.aligned.m16n8k8.row.col.f32.tf32.tf32.f32 "
        "{%0,%1,%2,%3}, {%4,%5,%6,%7}, {%8,%9}, {%0,%1,%2,%3};"
        : "+f"(c[0]), "+f"(c[1]), "+f"(c[2]), "+f"(c[3])
        : "r"(a[0]), "r"(a[1]), "r"(a[2]), "r"(a[3]), "r"(b[0]), "r"(b[1]));
}

// Shared warp-level MMA over one staged k16 chunk.
// Warp tile: 32 rows x 64 cols. c[mf][nf][4].
__device__ __forceinline__ void warp_mma_chunk(
    const uint32_t (*__restrict__ As)[20], const uint32_t (*__restrict__ Bs)[132],
    int warp_m, int warp_n, int g, int tig, float c[2][8][4])
{
    #pragma unroll
    for (int kk = 0; kk < 16; kk += 8) {
        uint32_t a[2][4];
        #pragma unroll
        for (int mf = 0; mf < 2; mf++) {
            int rb = warp_m * 32 + mf * 16;
            a[mf][0] = As[rb + g][kk + tig];
            a[mf][1] = As[rb + g + 8][kk + tig];
            a[mf][2] = As[rb + g][kk + tig + 4];
            a[mf][3] = As[rb + g + 8][kk + tig + 4];
        }
        #pragma unroll
        for (int nf = 0; nf < 8; nf++) {
            int cb = warp_n * 64 + nf * 8 + g;
            uint32_t b[2];
            b[0] = Bs[kk + tig][cb];
            b[1] = Bs[kk + tig + 4][cb];
            mma8(c[0][nf], a[0], b);
            mma8(c[1][nf], a[1], b);
        }
    }
}

// ===========================================================================
// GEMM1/GEMM2 (tf32 tensor cores).
// MODE 0: A[r,k] = x[b, k, n], r = b*16+n  -> writes g_S1 (rows r)
// MODE 1: A = g_S1 row-major               -> writes g_Sh PERMUTED (m = n*1024+b)
// ===========================================================================
template <int MODE>
__global__ __launch_bounds__(256)
void gemm_lrelu_tc(const float* __restrict__ Ain,
                   const float* __restrict__ W,
                   const float* __restrict__ bias)
{
    __shared__ uint32_t As[128][20];
    __shared__ uint32_t Bs[16][132];

    const int tid    = threadIdx.x;
    const int wid    = tid >> 5;
    const int lane   = tid & 31;
    const int g      = lane >> 2;       // groupID
    const int tig    = lane & 3;        // thread in group
    const int warp_m = wid >> 1;        // 0..3
    const int warp_n = wid & 1;         // 0..1
    const int row0   = blockIdx.x * 128;
    const int col0   = blockIdx.y * 128;

    const float* A = (MODE == 0) ? Ain : g_S1;
    float*       C = (MODE == 0) ? g_S1 : g_Sh;

    float c[2][8][4];
    #pragma unroll
    for (int i = 0; i < 2; i++)
        #pragma unroll
        for (int j = 0; j < 8; j++)
            #pragma unroll
            for (int q = 0; q < 4; q++) c[i][j][q] = 0.f;

    for (int k0 = 0; k0 < DD; k0 += 16) {
        // --- stage A (128 x 16) ---
        if (MODE == 0) {
            #pragma unroll
            for (int i = 0; i < 8; i++) {
                int e = tid + i * 256;
                int r = e >> 4, k = e & 15;
                int gr = row0 + r;
                int b  = gr >> 4, nn = gr & 15;
                As[r][k] = f2tf32(A[(size_t)b * (DD * NN) + (size_t)(k0 + k) * NN + nn]);
            }
        } else {
            #pragma unroll
            for (int i = 0; i < 2; i++) {
                int e = tid + i * 256;
                int r = e >> 2, c4 = e & 3;
                float4 v = *reinterpret_cast<const float4*>(
                    &A[(size_t)(row0 + r) * DD + k0 + c4 * 4]);
                As[r][c4 * 4 + 0] = f2tf32(v.x);
                As[r][c4 * 4 + 1] = f2tf32(v.y);
                As[r][c4 * 4 + 2] = f2tf32(v.z);
                As[r][c4 * 4 + 3] = f2tf32(v.w);
            }
        }
        // --- stage B (16 x 128), W row-major ld=DD ---
        #pragma unroll
        for (int i = 0; i < 2; i++) {
            int e = tid + i * 256;
            int k = e >> 5, c4 = e & 31;
            float4 v = *reinterpret_cast<const float4*>(
                &W[(size_t)(k0 + k) * DD + col0 + c4 * 4]);
            Bs[k][c4 * 4 + 0] = f2tf32(v.x);
            Bs[k][c4 * 4 + 1] = f2tf32(v.y);
            Bs[k][c4 * 4 + 2] = f2tf32(v.z);
            Bs[k][c4 * 4 + 3] = f2tf32(v.w);
        }
        __syncthreads();
        warp_mma_chunk(As, Bs, warp_m, warp_n, g, tig, c);
        __syncthreads();
    }

    // --- epilogue: bias + lrelu ---
    #pragma unroll
    for (int mf = 0; mf < 2; mf++) {
        #pragma unroll
        for (int half = 0; half < 2; half++) {           // row groupID / groupID+8
            int r = row0 + warp_m * 32 + mf * 16 + g + half * 8;
            size_t orow = (MODE == 0) ? (size_t)r
                                      : (size_t)((r & 15) * 1024 + (r >> 4));
            #pragma unroll
            for (int nf = 0; nf < 8; nf++) {
                int col = col0 + warp_n * 64 + nf * 8 + 2 * tig;
                float2 v;
                v.x = lrelu(c[mf][nf][half * 2 + 0] + bias[col]);
                v.y = lrelu(c[mf][nf][half * 2 + 1] + bias[col + 1]);
                *reinterpret_cast<float2*>(&C[orow * DD + col]) = v;
            }
        }
    }
}

// ===========================================================================
// GEMM3: tf32 fused classifier. grid (m-tiles, h-blocks, heads).
//   acc = full_in[m,:] @ Wc1[n,:,h0:h0+128]
//   logits[m*16+n] += sum_h lrelu(acc + bc1)*Wc2   (shfl-reduce + atomicAdd)
// (g_Sh is already permuted: full_in row m == g_Sh row m)
// ===========================================================================
__global__ __launch_bounds__(256)
void gemm_head_tc(const float* __restrict__ Wc1,
                  const float* __restrict__ bc1,
                  const float* __restrict__ Wc2,
                  float* __restrict__ logits)
{
    __shared__ uint32_t As[128][20];
    __shared__ uint32_t Bs[16][132];

    const int tid    = threadIdx.x;
    const int wid    = tid >> 5;
    const int lane   = tid & 31;
    const int g      = lane >> 2;
    const int tig    = lane & 3;
    const int warp_m = wid >> 1;
    const int warp_n = wid & 1;
    const int row0   = blockIdx.x * 128;
    const int h0     = blockIdx.y * 128;
    const int n      = blockIdx.z;
    const float* __restrict__ W = Wc1 + (size_t)n * DD * HH;

    float c[2][8][4];
    #pragma unroll
    for (int i = 0; i < 2; i++)
        #pragma unroll
        for (int j = 0; j < 8; j++)
            #pragma unroll
            for (int q = 0; q < 4; q++) c[i][j][q] = 0.f;

    for (int k0 = 0; k0 < DD; k0 += 16) {
        #pragma unroll
        for (int i = 0; i < 2; i++) {
            int e = tid + i * 256;
            int r = e >> 2, c4 = e & 3;
            float4 v = *reinterpret_cast<const float4*>(
                &g_Sh[(size_t)(row0 + r) * DD + k0 + c4 * 4]);
            As[r][c4 * 4 + 0] = f2tf32(v.x);
            As[r][c4 * 4 + 1] = f2tf32(v.y);
            As[r][c4 * 4 + 2] = f2tf32(v.z);
            As[r][c4 * 4 + 3] = f2tf32(v.w);
        }
        #pragma unroll
        for (int i = 0; i < 2; i++) {
            int e = tid + i * 256;
            int k = e >> 5, c4 = e & 31;
            float4 v = *reinterpret_cast<const float4*>(
                &W[(size_t)(k0 + k) * HH + h0 + c4 * 4]);
            Bs[k][c4 * 4 + 0] = f2tf32(v.x);
            Bs[k][c4 * 4 + 1] = f2tf32(v.y);
            Bs[k][c4 * 4 + 2] = f2tf32(v.z);
            Bs[k][c4 * 4 + 3] = f2tf32(v.w);
        }
        __syncthreads();
        warp_mma_chunk(As, Bs, warp_m, warp_n, g, tig, c);
        __syncthreads();
    }

    // --- fused epilogue: lrelu(+bc1) * Wc2, reduce over h, atomic into logits ---
    float p[4] = {0.f, 0.f, 0.f, 0.f};    // rows: mf*16 + {g, g+8}
    #pragma unroll
    for (int nf = 0; nf < 8; nf++) {
        int h = h0 + warp_n * 64 + nf * 8 + 2 * tig;
        float b1a = bc1[n * HH + h],     b1b = bc1[n * HH + h + 1];
        float w2a = Wc2[n * HH + h],     w2b = Wc2[n * HH + h + 1];
        #pragma unroll
        for (int mf = 0; mf < 2; mf++) {
            p[2 * mf + 0] += lrelu(c[mf][nf][0] + b1a) * w2a
                           + lrelu(c[mf][nf][1] + b1b) * w2b;
            p[2 * mf + 1] += lrelu(c[mf][nf][2] + b1a) * w2a
                           + lrelu(c[mf][nf][3] + b1b) * w2b;
        }
    }
    #pragma unroll
    for (int i = 0; i < 4; i++) {
        float v = p[i];
        v += __shfl_xor_sync(0xffffffffu, v, 1);
        v += __shfl_xor_sync(0xffffffffu, v, 2);
        if (tig == 0) {
            int mf = i >> 1, half = i & 1;
            int r = row0 + warp_m * 32 + mf * 16 + g + half * 8;
            atomicAdd(&logits[r * NN + n], v);
        }
    }
}

__global__ void zero_kernel(float* __restrict__ p, int n)
{
    int i = blockIdx.x * 256 + threadIdx.x;
    if (i < n) p[i] = 0.f;
}

// full_out += bc2; out[b,n] = sigmoid(diagonal of full_out)
__global__ void finalize_kernel(float* __restrict__ out,
                                const float* __restrict__ bc2)
{
    int idx = blockIdx.x * 256 + threadIdx.x;      // < 262144
    int m = idx >> 4, n = idx & 15;
    float* full = out + MTOT;
    float v = full[idx] + bc2[n];
    full[idx] = v;
    if ((m >> 10) == n) {                           // m = n*1024 + b
        int b = m & 1023;
        out[b * NN + n] = 1.f / (1.f + expf(-v));
    }
}

extern "C" void kernel_launch(void* const* d_in, const int* in_sizes, int n_in,
                              void* d_out, int out_size)
{
    const float* x   = (const float*)d_in[0];
    const float* Ws1 = (const float*)d_in[1];
    const float* bs1 = (const float*)d_in[2];
    const float* Ws2 = (const float*)d_in[3];
    const float* bs2 = (const float*)d_in[4];
    const float* Wc1 = (const float*)d_in[5];
    const float* bc1 = (const float*)d_in[6];
    const float* Wc2 = (const float*)d_in[7];
    const float* bc2 = (const float*)d_in[8];
    float* out = (float*)d_out;

    dim3 blk(256);
    gemm_lrelu_tc<0><<<dim3(MTOT / 128, DD / 128), blk>>>(x, Ws1, bs1);
    gemm_lrelu_tc<1><<<dim3(MTOT / 128, DD / 128), blk>>>(nullptr, Ws2, bs2);
    zero_kernel<<<(MTOT * NN + 255) / 256, blk>>>(out + MTOT, MTOT * NN);
    gemm_head_tc<<<dim3(MTOT / 128, HH / 128, NN), blk>>>(Wc1, bc1, Wc2, out + MTOT);
    finalize_kernel<<<(MTOT * NN + 255) / 256, blk>>>(out, bc2);
}

// round 7
// speedup vs baseline: 2.3314x; 1.1073x over previous
#include <cuda_runtime.h>
#include <math.h>
#include <stdint.h>

// B=1024, D=512, N=16, H=512, M = N*B = 16384
#define DD   512
#define NN   16
#define HH   512
#define MTOT 16384

// Scratch (static __device__ — no allocations allowed)
__device__ float g_S1[MTOT * DD];   // lrelu(xT @ Ws1 + bs1), rows r = b*16+n
__device__ float g_Sh[MTOT * DD];   // shared, PERMUTED rows: m = n*1024 + b

__device__ __forceinline__ float lrelu(float v) { return v >= 0.f ? v : 0.1f * v; }

__device__ __forceinline__ uint32_t f2tf32(float f) {
    uint32_t u;
    asm("cvt.rna.tf32.f32 %0, %1;" : "=r"(u) : "f"(f));
    return u;
}

__device__ __forceinline__ void mma8(float* c, const uint32_t* a, const uint32_t* b) {
    asm volatile(
        "mma.sync.aligned.m16n8k8.row.col.f32.tf32.tf32.f32 "
        "{%0,%1,%2,%3}, {%4,%5,%6,%7}, {%8,%9}, {%0,%1,%2,%3};"
        : "+f"(c[0]), "+f"(c[1]), "+f"(c[2]), "+f"(c[3])
        : "r"(a[0]), "r"(a[1]), "r"(a[2]), "r"(a[3]), "r"(b[0]), "r"(b[1]));
}

// Shared warp-level MMA over one staged k16 chunk (R3-verbatim).
// Warp tile: 32 rows x 64 cols. c[mf][nf][4].
__device__ __forceinline__ void warp_mma_chunk(
    const uint32_t (*__restrict__ As)[20], const uint32_t (*__restrict__ Bs)[132],
    int warp_m, int warp_n, int g, int tig, float c[2][8][4])
{
    #pragma unroll
    for (int kk = 0; kk < 16; kk += 8) {
        uint32_t a[2][4];
        #pragma unroll
        for (int mf = 0; mf < 2; mf++) {
            int rb = warp_m * 32 + mf * 16;
            a[mf][0] = As[rb + g][kk + tig];
            a[mf][1] = As[rb + g + 8][kk + tig];
            a[mf][2] = As[rb + g][kk + tig + 4];
            a[mf][3] = As[rb + g + 8][kk + tig + 4];
        }
        #pragma unroll
        for (int nf = 0; nf < 8; nf++) {
            int cb = warp_n * 64 + nf * 8 + g;
            uint32_t b[2];
            b[0] = Bs[kk + tig][cb];
            b[1] = Bs[kk + tig + 4][cb];
            mma8(c[0][nf], a[0], b);
            mma8(c[1][nf], a[1], b);
        }
    }
}

// ===========================================================================
// GEMM1/GEMM2 (R3-verbatim).
// MODE 0: A[r,k] = x[b, k, n], r = b*16+n  -> writes g_S1 (rows r)
// MODE 1: A = g_S1 row-major               -> writes g_Sh PERMUTED (m = n*1024+b)
// ===========================================================================
template <int MODE>
__global__ __launch_bounds__(256)
void gemm_lrelu_tc(const float* __restrict__ Ain,
                   const float* __restrict__ W,
                   const float* __restrict__ bias)
{
    __shared__ uint32_t As[128][20];
    __shared__ uint32_t Bs[16][132];

    const int tid    = threadIdx.x;
    const int wid    = tid >> 5;
    const int lane   = tid & 31;
    const int g      = lane >> 2;
    const int tig    = lane & 3;
    const int warp_m = wid >> 1;
    const int warp_n = wid & 1;
    const int row0   = blockIdx.x * 128;
    const int col0   = blockIdx.y * 128;

    const float* A = (MODE == 0) ? Ain : g_S1;
    float*       C = (MODE == 0) ? g_S1 : g_Sh;

    float c[2][8][4];
    #pragma unroll
    for (int i = 0; i < 2; i++)
        #pragma unroll
        for (int j = 0; j < 8; j++)
            #pragma unroll
            for (int q = 0; q < 4; q++) c[i][j][q] = 0.f;

    for (int k0 = 0; k0 < DD; k0 += 16) {
        if (MODE == 0) {
            #pragma unroll
            for (int i = 0; i < 8; i++) {
                int e = tid + i * 256;
                int r = e >> 4, k = e & 15;
                int gr = row0 + r;
                int b  = gr >> 4, nn = gr & 15;
                As[r][k] = f2tf32(A[(size_t)b * (DD * NN) + (size_t)(k0 + k) * NN + nn]);
            }
        } else {
            #pragma unroll
            for (int i = 0; i < 2; i++) {
                int e = tid + i * 256;
                int r = e >> 2, c4 = e & 3;
                float4 v = *reinterpret_cast<const float4*>(
                    &A[(size_t)(row0 + r) * DD + k0 + c4 * 4]);
                As[r][c4 * 4 + 0] = f2tf32(v.x);
                As[r][c4 * 4 + 1] = f2tf32(v.y);
                As[r][c4 * 4 + 2] = f2tf32(v.z);
                As[r][c4 * 4 + 3] = f2tf32(v.w);
            }
        }
        #pragma unroll
        for (int i = 0; i < 2; i++) {
            int e = tid + i * 256;
            int k = e >> 5, c4 = e & 31;
            float4 v = *reinterpret_cast<const float4*>(
                &W[(size_t)(k0 + k) * DD + col0 + c4 * 4]);
            Bs[k][c4 * 4 + 0] = f2tf32(v.x);
            Bs[k][c4 * 4 + 1] = f2tf32(v.y);
            Bs[k][c4 * 4 + 2] = f2tf32(v.z);
            Bs[k][c4 * 4 + 3] = f2tf32(v.w);
        }
        __syncthreads();
        warp_mma_chunk(As, Bs, warp_m, warp_n, g, tig, c);
        __syncthreads();
    }

    #pragma unroll
    for (int mf = 0; mf < 2; mf++) {
        #pragma unroll
        for (int half = 0; half < 2; half++) {
            int r = row0 + warp_m * 32 + mf * 16 + g + half * 8;
            size_t orow = (MODE == 0) ? (size_t)r
                                      : (size_t)((r & 15) * 1024 + (r >> 4));
            #pragma unroll
            for (int nf = 0; nf < 8; nf++) {
                int col = col0 + warp_n * 64 + nf * 8 + 2 * tig;
                float2 v;
                v.x = lrelu(c[mf][nf][half * 2 + 0] + bias[col]);
                v.y = lrelu(c[mf][nf][half * 2 + 1] + bias[col + 1]);
                *reinterpret_cast<float2*>(&C[orow * DD + col]) = v;
            }
        }
    }
}

// ===========================================================================
// GEMM3: same structure as R3 (grid (128 m, 4 h, 16 n), atomicAdd epilogue,
// k-accumulation order 0,8,16,24,...) but internals use fragment-slotted
// SMEM so each thread's 4 fragment regs are one ld.shared.v4.
//
// A slot (wm,mf,cc): 32 lanes x 4 regs (+8 pad) = 136 u32. Lane t holds
//   {A[m][k], A[m+8][k], A[m][k+4], A[m+8][k+4]},
//   m = wm*32+mf*16+t/4, k = cc*8+t%4 (k local to the 32-wide stage).
// B slot (cc,wn,np): lane t holds {B[k][n], B[k+4][n], B[k][n+8], B[k+4][n+8]},
//   n = wn*64+np*16+t/4, k = cc*8+t%4.
// ===========================================================================
#define SLOT 136

__global__ __launch_bounds__(256)
void gemm_head_tc(const float* __restrict__ Wc1,
                  const float* __restrict__ bc1,
                  const float* __restrict__ Wc2,
                  float* __restrict__ logits)
{
    __shared__ uint32_t Asl[32 * SLOT];
    __shared__ uint32_t Bsl[32 * SLOT];

    const int tid  = threadIdx.x;
    const int wid  = tid >> 5;
    const int lane = tid & 31;
    const int g    = lane >> 2;
    const int tig  = lane & 3;
    const int wm   = wid >> 1;
    const int wn   = wid & 1;
    const int row0 = blockIdx.x * 128;
    const int h0   = blockIdx.y * 128;
    const int n    = blockIdx.z;
    const float* __restrict__ W = Wc1 + (size_t)n * DD * HH;

    float c[2][8][4];
    #pragma unroll
    for (int i = 0; i < 2; i++)
        #pragma unroll
        for (int j = 0; j < 8; j++)
            #pragma unroll
            for (int q = 0; q < 4; q++) c[i][j][q] = 0.f;

    for (int k0 = 0; k0 < DD; k0 += 32) {
        // --- stage A: 128 rows x 32 k, slotted ---
        #pragma unroll
        for (int i = 0; i < 4; i++) {
            int e = tid + i * 256;            // 0..1023
            int r = e >> 3, q = e & 7;        // row, float4 index (k = q*4+w)
            float4 v = *reinterpret_cast<const float4*>(
                &g_Sh[(size_t)(row0 + r) * DD + k0 + q * 4]);
            int base = (((r >> 5) * 2 + ((r >> 4) & 1)) * 4 + (q >> 1)) * SLOT
                     + (r & 7) * 16 + ((r >> 3) & 1) + 2 * (q & 1);
            Asl[base + 0]  = f2tf32(v.x);
            Asl[base + 4]  = f2tf32(v.y);
            Asl[base + 8]  = f2tf32(v.z);
            Asl[base + 12] = f2tf32(v.w);
        }
        // --- stage B: 32 k-rows x 128 h, slotted ---
        #pragma unroll
        for (int i = 0; i < 4; i++) {
            int e = tid + i * 256;            // 0..1023
            int kl = e >> 5, nq = e & 31;     // k-row, float4 index (n = nq*4+j)
            float4 v = *reinterpret_cast<const float4*>(
                &W[(size_t)(k0 + kl) * HH + h0 + nq * 4]);
            float vv[4] = {v.x, v.y, v.z, v.w};
            #pragma unroll
            for (int j = 0; j < 4; j++) {
                int nn = nq * 4 + j;
                int idx = (((kl >> 3) * 2 + (nn >> 6)) * 4 + ((nn >> 4) & 3)) * SLOT
                        + (nn & 7) * 16 + (kl & 3) * 4
                        + ((kl >> 2) & 1) + 2 * ((nn >> 3) & 1);
                Bsl[idx] = f2tf32(vv[j]);
            }
        }
        __syncthreads();

        // --- mma from slots: vector fragment loads ---
        #pragma unroll
        for (int cc = 0; cc < 4; cc++) {
            uint4 af[2];
            #pragma unroll
            for (int mf = 0; mf < 2; mf++)
                af[mf] = *reinterpret_cast<const uint4*>(
                    &Asl[((wm * 2 + mf) * 4 + cc) * SLOT + lane * 4]);
            uint4 bf[4];
            #pragma unroll
            for (int np = 0; np < 4; np++)
                bf[np] = *reinterpret_cast<const uint4*>(
                    &Bsl[((cc * 2 + wn) * 4 + np) * SLOT + lane * 4]);
            #pragma unroll
            for (int np = 0; np < 4; np++) {
                const uint32_t* bb = reinterpret_cast<const uint32_t*>(&bf[np]);
                #pragma unroll
                for (int mf = 0; mf < 2; mf++) {
                    const uint32_t* aa = reinterpret_cast<const uint32_t*>(&af[mf]);
                    mma8(c[mf][2 * np + 0], aa, bb);
                    mma8(c[mf][2 * np + 1], aa, bb + 2);
                }
            }
        }
        __syncthreads();
    }

    // --- fused epilogue (R3-verbatim): lrelu(+bc1)*Wc2, shfl reduce, atomicAdd ---
    float p[4] = {0.f, 0.f, 0.f, 0.f};
    #pragma unroll
    for (int nf = 0; nf < 8; nf++) {
        int h = h0 + wn * 64 + nf * 8 + 2 * tig;
        float b1a = bc1[n * HH + h],     b1b = bc1[n * HH + h + 1];
        float w2a = Wc2[n * HH + h],     w2b = Wc2[n * HH + h + 1];
        #pragma unroll
        for (int mf = 0; mf < 2; mf++) {
            p[2 * mf + 0] += lrelu(c[mf][nf][0] + b1a) * w2a
                           + lrelu(c[mf][nf][1] + b1b) * w2b;
            p[2 * mf + 1] += lrelu(c[mf][nf][2] + b1a) * w2a
                           + lrelu(c[mf][nf][3] + b1b) * w2b;
        }
    }
    #pragma unroll
    for (int i = 0; i < 4; i++) {
        float v = p[i];
        v += __shfl_xor_sync(0xffffffffu, v, 1);
        v += __shfl_xor_sync(0xffffffffu, v, 2);
        if (tig == 0) {
            int mf = i >> 1, half = i & 1;
            int r = row0 + wm * 32 + mf * 16 + g + half * 8;
            atomicAdd(&logits[r * NN + n], v);
        }
    }
}

__global__ void zero_kernel(float* __restrict__ p, int n)
{
    int i = blockIdx.x * 256 + threadIdx.x;
    if (i < n) p[i] = 0.f;
}

// full_out += bc2; out[b,n] = sigmoid(diagonal of full_out)  (R3-verbatim)
__global__ void finalize_kernel(float* __restrict__ out,
                                const float* __restrict__ bc2)
{
    int idx = blockIdx.x * 256 + threadIdx.x;      // < 262144
    int m = idx >> 4, n = idx & 15;
    float* full = out + MTOT;
    float v = full[idx] + bc2[n];
    full[idx] = v;
    if ((m >> 10) == n) {                           // m = n*1024 + b
        int b = m & 1023;
        out[b * NN + n] = 1.f / (1.f + expf(-v));
    }
}

extern "C" void kernel_launch(void* const* d_in, const int* in_sizes, int n_in,
                              void* d_out, int out_size)
{
    const float* x   = (const float*)d_in[0];
    const float* Ws1 = (const float*)d_in[1];
    const float* bs1 = (const float*)d_in[2];
    const float* Ws2 = (const float*)d_in[3];
    const float* bs2 = (const float*)d_in[4];
    const float* Wc1 = (const float*)d_in[5];
    const float* bc1 = (const float*)d_in[6];
    const float* Wc2 = (const float*)d_in[7];
    const float* bc2 = (const float*)d_in[8];
    float* out = (float*)d_out;

    dim3 blk(256);
    gemm_lrelu_tc<0><<<dim3(MTOT / 128, DD / 128), blk>>>(x, Ws1, bs1);
    gemm_lrelu_tc<1><<<dim3(MTOT / 128, DD / 128), blk>>>(nullptr, Ws2, bs2);
    zero_kernel<<<(MTOT * NN + 255) / 256, blk>>>(out + MTOT, MTOT * NN);
    gemm_head_tc<<<dim3(MTOT / 128, HH / 128, NN), blk>>>(Wc1, bc1, Wc2, out + MTOT);
    finalize_kernel<<<(MTOT * NN + 255) / 256, blk>>>(out, bc2);
}

// round 8
// speedup vs baseline: 2.6241x; 1.1255x over previous
#include <cuda_runtime.h>
#include <math.h>
#include <stdint.h>

// B=1024, D=512, N=16, H=512, M = N*B = 16384
#define DD   512
#define NN   16
#define HH   512
#define MTOT 16384

// Scratch (static __device__ — no allocations allowed)
__device__ float g_S1[MTOT * DD];   // lrelu(xT @ Ws1 + bs1), rows r = b*16+n
__device__ float g_Sh[MTOT * DD];   // shared, PERMUTED rows: m = n*1024 + b

__device__ __forceinline__ float lrelu(float v) { return v >= 0.f ? v : 0.1f * v; }

__device__ __forceinline__ uint32_t f2tf32(float f) {
    uint32_t u;
    asm("cvt.rna.tf32.f32 %0, %1;" : "=r"(u) : "f"(f));
    return u;
}

__device__ __forceinline__ void mma8(float* c, const uint32_t* a, const uint32_t* b) {
    asm volatile(
        "mma.sync.aligned.m16n8k8.row.col.f32.tf32.tf32.f32 "
        "{%0,%1,%2,%3}, {%4,%5,%6,%7}, {%8,%9}, {%0,%1,%2,%3};"
        : "+f"(c[0]), "+f"(c[1]), "+f"(c[2]), "+f"(c[3])
        : "r"(a[0]), "r"(a[1]), "r"(a[2]), "r"(a[3]), "r"(b[0]), "r"(b[1]));
}

// Shared warp-level MMA over one staged k16 chunk (R3-verbatim).
// Warp tile: 32 rows x 64 cols. c[mf][nf][4].
__device__ __forceinline__ void warp_mma_chunk(
    const uint32_t (*__restrict__ As)[20], const uint32_t (*__restrict__ Bs)[132],
    int warp_m, int warp_n, int g, int tig, float c[2][8][4])
{
    #pragma unroll
    for (int kk = 0; kk < 16; kk += 8) {
        uint32_t a[2][4];
        #pragma unroll
        for (int mf = 0; mf < 2; mf++) {
            int rb = warp_m * 32 + mf * 16;
            a[mf][0] = As[rb + g][kk + tig];
            a[mf][1] = As[rb + g + 8][kk + tig];
            a[mf][2] = As[rb + g][kk + tig + 4];
            a[mf][3] = As[rb + g + 8][kk + tig + 4];
        }
        #pragma unroll
        for (int nf = 0; nf < 8; nf++) {
            int cb = warp_n * 64 + nf * 8 + g;
            uint32_t b[2];
            b[0] = Bs[kk + tig][cb];
            b[1] = Bs[kk + tig + 4][cb];
            mma8(c[0][nf], a[0], b);
            mma8(c[1][nf], a[1], b);
        }
    }
}

// ===========================================================================
// GEMM1/GEMM2 (R3-verbatim).
// MODE 0: A[r,k] = x[b, k, n], r = b*16+n  -> writes g_S1 (rows r)
// MODE 1: A = g_S1 row-major               -> writes g_Sh PERMUTED (m = n*1024+b)
// ===========================================================================
template <int MODE>
__global__ __launch_bounds__(256)
void gemm_lrelu_tc(const float* __restrict__ Ain,
                   const float* __restrict__ W,
                   const float* __restrict__ bias)
{
    __shared__ uint32_t As[128][20];
    __shared__ uint32_t Bs[16][132];

    const int tid    = threadIdx.x;
    const int wid    = tid >> 5;
    const int lane   = tid & 31;
    const int g      = lane >> 2;
    const int tig    = lane & 3;
    const int warp_m = wid >> 1;
    const int warp_n = wid & 1;
    const int row0   = blockIdx.x * 128;
    const int col0   = blockIdx.y * 128;

    const float* A = (MODE == 0) ? Ain : g_S1;
    float*       C = (MODE == 0) ? g_S1 : g_Sh;

    float c[2][8][4];
    #pragma unroll
    for (int i = 0; i < 2; i++)
        #pragma unroll
        for (int j = 0; j < 8; j++)
            #pragma unroll
            for (int q = 0; q < 4; q++) c[i][j][q] = 0.f;

    for (int k0 = 0; k0 < DD; k0 += 16) {
        if (MODE == 0) {
            #pragma unroll
            for (int i = 0; i < 8; i++) {
                int e = tid + i * 256;
                int r = e >> 4, k = e & 15;
                int gr = row0 + r;
                int b  = gr >> 4, nn = gr & 15;
                As[r][k] = f2tf32(A[(size_t)b * (DD * NN) + (size_t)(k0 + k) * NN + nn]);
            }
        } else {
            #pragma unroll
            for (int i = 0; i < 2; i++) {
                int e = tid + i * 256;
                int r = e >> 2, c4 = e & 3;
                float4 v = *reinterpret_cast<const float4*>(
                    &A[(size_t)(row0 + r) * DD + k0 + c4 * 4]);
                As[r][c4 * 4 + 0] = f2tf32(v.x);
                As[r][c4 * 4 + 1] = f2tf32(v.y);
                As[r][c4 * 4 + 2] = f2tf32(v.z);
                As[r][c4 * 4 + 3] = f2tf32(v.w);
            }
        }
        #pragma unroll
        for (int i = 0; i < 2; i++) {
            int e = tid + i * 256;
            int k = e >> 5, c4 = e & 31;
            float4 v = *reinterpret_cast<const float4*>(
                &W[(size_t)(k0 + k) * DD + col0 + c4 * 4]);
            Bs[k][c4 * 4 + 0] = f2tf32(v.x);
            Bs[k][c4 * 4 + 1] = f2tf32(v.y);
            Bs[k][c4 * 4 + 2] = f2tf32(v.z);
            Bs[k][c4 * 4 + 3] = f2tf32(v.w);
        }
        __syncthreads();
        warp_mma_chunk(As, Bs, warp_m, warp_n, g, tig, c);
        __syncthreads();
    }

    #pragma unroll
    for (int mf = 0; mf < 2; mf++) {
        #pragma unroll
        for (int half = 0; half < 2; half++) {
            int r = row0 + warp_m * 32 + mf * 16 + g + half * 8;
            size_t orow = (MODE == 0) ? (size_t)r
                                      : (size_t)((r & 15) * 1024 + (r >> 4));
            #pragma unroll
            for (int nf = 0; nf < 8; nf++) {
                int col = col0 + warp_n * 64 + nf * 8 + 2 * tig;
                float2 v;
                v.x = lrelu(c[mf][nf][half * 2 + 0] + bias[col]);
                v.y = lrelu(c[mf][nf][half * 2 + 1] + bias[col + 1]);
                *reinterpret_cast<float2*>(&C[orow * DD + col]) = v;
            }
        }
    }
}

// ===========================================================================
// GEMM3: slotted SMEM (R7 layout, staging byte-identical), but 4 warps of
// 64x64 tiles (2x2 warp grid) instead of 8 warps of 32x64 (4x2).
// A-fragment redundancy Wn: 2 -> 2 ; B-fragment redundancy Wm: 4 -> 2.
// LDS per k8-chunk: 24KB -> 16KB (1.5x less SMEM read traffic).
//
// A slot (mgroup=r>>4, cc): 32 lanes x 4 regs (+8 pad) = 136 u32. Lane t:
//   {A[m][k], A[m+8][k], A[m][k+4], A[m+8][k+4]}, m = mgroup*16+t/4, k=cc*8+t%4.
// B slot (cc, wn, np): lane t: {B[k][n], B[k+4][n], B[k][n+8], B[k+4][n+8]},
//   n = wn*64+np*16+t/4, k = cc*8+t%4.
// ===========================================================================
#define SLOT 136

__global__ __launch_bounds__(128)
void gemm_head_tc(const float* __restrict__ Wc1,
                  const float* __restrict__ bc1,
                  const float* __restrict__ Wc2,
                  float* __restrict__ logits)
{
    __shared__ uint32_t Asl[32 * SLOT];
    __shared__ uint32_t Bsl[32 * SLOT];

    const int tid  = threadIdx.x;       // 128 threads, 4 warps
    const int wid  = tid >> 5;
    const int lane = tid & 31;
    const int g    = lane >> 2;
    const int tig  = lane & 3;
    const int wm   = wid >> 1;          // 0..1 (64 rows each)
    const int wn   = wid & 1;           // 0..1 (64 cols each)
    const int row0 = blockIdx.x * 128;
    const int h0   = blockIdx.y * 128;
    const int n    = blockIdx.z;
    const float* __restrict__ W = Wc1 + (size_t)n * DD * HH;

    float c[4][8][4];
    #pragma unroll
    for (int i = 0; i < 4; i++)
        #pragma unroll
        for (int j = 0; j < 8; j++)
            #pragma unroll
            for (int q = 0; q < 4; q++) c[i][j][q] = 0.f;

    for (int k0 = 0; k0 < DD; k0 += 32) {
        // --- stage A: 128 rows x 32 k, slotted (same map as R7) ---
        #pragma unroll
        for (int i = 0; i < 8; i++) {
            int e = tid + i * 128;            // 0..1023
            int r = e >> 3, q = e & 7;        // row, float4 index (k = q*4+w)
            float4 v = *reinterpret_cast<const float4*>(
                &g_Sh[(size_t)(row0 + r) * DD + k0 + q * 4]);
            int base = ((r >> 4) * 4 + (q >> 1)) * SLOT
                     + (r & 7) * 16 + ((r >> 3) & 1) + 2 * (q & 1);
            Asl[base + 0]  = f2tf32(v.x);
            Asl[base + 4]  = f2tf32(v.y);
            Asl[base + 8]  = f2tf32(v.z);
            Asl[base + 12] = f2tf32(v.w);
        }
        // --- stage B: 32 k-rows x 128 h, slotted (same map as R7) ---
        #pragma unroll
        for (int i = 0; i < 8; i++) {
            int e = tid + i * 128;            // 0..1023
            int kl = e >> 5, nq = e & 31;     // k-row, float4 index (n = nq*4+j)
            float4 v = *reinterpret_cast<const float4*>(
                &W[(size_t)(k0 + kl) * HH + h0 + nq * 4]);
            float vv[4] = {v.x, v.y, v.z, v.w};
            #pragma unroll
            for (int j = 0; j < 4; j++) {
                int nn = nq * 4 + j;
                int idx = (((kl >> 3) * 2 + (nn >> 6)) * 4 + ((nn >> 4) & 3)) * SLOT
                        + (nn & 7) * 16 + (kl & 3) * 4
                        + ((kl >> 2) & 1) + 2 * ((nn >> 3) & 1);
                Bsl[idx] = f2tf32(vv[j]);
            }
        }
        __syncthreads();

        // --- mma from slots: 64x64 warp tile ---
        #pragma unroll
        for (int cc = 0; cc < 4; cc++) {
            uint4 af[4];
            #pragma unroll
            for (int mf = 0; mf < 4; mf++)
                af[mf] = *reinterpret_cast<const uint4*>(
                    &Asl[((wm * 4 + mf) * 4 + cc) * SLOT + lane * 4]);
            uint4 bf[4];
            #pragma unroll
            for (int np = 0; np < 4; np++)
                bf[np] = *reinterpret_cast<const uint4*>(
                    &Bsl[((cc * 2 + wn) * 4 + np) * SLOT + lane * 4]);
            #pragma unroll
            for (int np = 0; np < 4; np++) {
                const uint32_t* bb = reinterpret_cast<const uint32_t*>(&bf[np]);
                #pragma unroll
                for (int mf = 0; mf < 4; mf++) {
                    const uint32_t* aa = reinterpret_cast<const uint32_t*>(&af[mf]);
                    mma8(c[mf][2 * np + 0], aa, bb);
                    mma8(c[mf][2 * np + 1], aa, bb + 2);
                }
            }
        }
        __syncthreads();
    }

    // --- fused epilogue: lrelu(+bc1)*Wc2, shfl reduce, atomicAdd ---
    float p[8];
    #pragma unroll
    for (int i = 0; i < 8; i++) p[i] = 0.f;
    #pragma unroll
    for (int nf = 0; nf < 8; nf++) {
        int h = h0 + wn * 64 + nf * 8 + 2 * tig;
        float b1a = bc1[n * HH + h],     b1b = bc1[n * HH + h + 1];
        float w2a = Wc2[n * HH + h],     w2b = Wc2[n * HH + h + 1];
        #pragma unroll
        for (int mf = 0; mf < 4; mf++) {
            p[2 * mf + 0] += lrelu(c[mf][nf][0] + b1a) * w2a
                           + lrelu(c[mf][nf][1] + b1b) * w2b;
            p[2 * mf + 1] += lrelu(c[mf][nf][2] + b1a) * w2a
                           + lrelu(c[mf][nf][3] + b1b) * w2b;
        }
    }
    #pragma unroll
    for (int i = 0; i < 8; i++) {
        float v = p[i];
        v += __shfl_xor_sync(0xffffffffu, v, 1);
        v += __shfl_xor_sync(0xffffffffu, v, 2);
        if (tig == 0) {
            int mf = i >> 1, half = i & 1;
            int r = row0 + wm * 64 + mf * 16 + g + half * 8;
            atomicAdd(&logits[r * NN + n], v);
        }
    }
}

__global__ void zero_kernel(float* __restrict__ p, int n)
{
    int i = blockIdx.x * 256 + threadIdx.x;
    if (i < n) p[i] = 0.f;
}

// full_out += bc2; out[b,n] = sigmoid(diagonal of full_out)  (R3-verbatim)
__global__ void finalize_kernel(float* __restrict__ out,
                                const float* __restrict__ bc2)
{
    int idx = blockIdx.x * 256 + threadIdx.x;      // < 262144
    int m = idx >> 4, n = idx & 15;
    float* full = out + MTOT;
    float v = full[idx] + bc2[n];
    full[idx] = v;
    if ((m >> 10) == n) {                           // m = n*1024 + b
        int b = m & 1023;
        out[b * NN + n] = 1.f / (1.f + expf(-v));
    }
}

extern "C" void kernel_launch(void* const* d_in, const int* in_sizes, int n_in,
                              void* d_out, int out_size)
{
    const float* x   = (const float*)d_in[0];
    const float* Ws1 = (const float*)d_in[1];
    const float* bs1 = (const float*)d_in[2];
    const float* Ws2 = (const float*)d_in[3];
    const float* bs2 = (const float*)d_in[4];
    const float* Wc1 = (const float*)d_in[5];
    const float* bc1 = (const float*)d_in[6];
    const float* Wc2 = (const float*)d_in[7];
    const float* bc2 = (const float*)d_in[8];
    float* out = (float*)d_out;

    dim3 blk(256);
    gemm_lrelu_tc<0><<<dim3(MTOT / 128, DD / 128), blk>>>(x, Ws1, bs1);
    gemm_lrelu_tc<1><<<dim3(MTOT / 128, DD / 128), blk>>>(nullptr, Ws2, bs2);
    zero_kernel<<<(MTOT * NN + 255) / 256, blk>>>(out + MTOT, MTOT * NN);
    gemm_head_tc<<<dim3(MTOT / 128, HH / 128, NN), dim3(128)>>>(Wc1, bc1, Wc2, out + MTOT);
    finalize_kernel<<<(MTOT * NN + 255) / 256, blk>>>(out, bc2);
}

// round 9
// speedup vs baseline: 3.6729x; 1.3997x over previous
#include <cuda_runtime.h>
#include <math.h>
#include <stdint.h>

// B=1024, D=512, N=16, H=512, M = N*B = 16384
#define DD   512
#define NN   16
#define HH   512
#define MTOT 16384

// Scratch (static __device__ — no allocations allowed)
__device__ float g_S1[MTOT * DD];   // lrelu(xT @ Ws1 + bs1), rows r = b*16+n
__device__ float g_Sh[MTOT * DD];   // shared, PERMUTED rows: m = n*1024 + b
// Pre-slotted tf32 operands for GEMM3:
//   g_A[tile(128)][kc(16)][slot(32)][128]  from g_Sh
//   g_B[n*4+hb(64)][kc(16)][slot(32)][128] from Wc1
__device__ uint32_t g_A[128 * 16 * 32 * 128];
__device__ uint32_t g_B[64  * 16 * 32 * 128];

__device__ __forceinline__ float lrelu(float v) { return v >= 0.f ? v : 0.1f * v; }

__device__ __forceinline__ uint32_t f2tf32(float f) {
    uint32_t u;
    asm("cvt.rna.tf32.f32 %0, %1;" : "=r"(u) : "f"(f));
    return u;
}
__device__ __forceinline__ uint32_t smem_u32(const void* p) {
    uint32_t a;
    asm("{ .reg .u64 t; cvta.to.shared.u64 t, %1; cvt.u32.u64 %0, t; }" : "=r"(a) : "l"(p));
    return a;
}
__device__ __forceinline__ void cpcg16(uint32_t dst, const void* src) {
    asm volatile("cp.async.cg.shared.global [%0], [%1], 16;" :: "r"(dst), "l"(src));
}
__device__ __forceinline__ void cp_commit() {
    asm volatile("cp.async.commit_group;" ::: "memory");
}
template <int N>
__device__ __forceinline__ void cp_wait() {
    asm volatile("cp.async.wait_group %0;" :: "n"(N) : "memory");
}

__device__ __forceinline__ void mma8(float* c, const uint32_t* a, const uint32_t* b) {
    asm volatile(
        "mma.sync.aligned.m16n8k8.row.col.f32.tf32.tf32.f32 "
        "{%0,%1,%2,%3}, {%4,%5,%6,%7}, {%8,%9}, {%0,%1,%2,%3};"
        : "+f"(c[0]), "+f"(c[1]), "+f"(c[2]), "+f"(c[3])
        : "r"(a[0]), "r"(a[1]), "r"(a[2]), "r"(a[3]), "r"(b[0]), "r"(b[1]));
}

// Shared warp-level MMA over one staged k16 chunk (R3-verbatim, for GEMM1/2).
__device__ __forceinline__ void warp_mma_chunk(
    const uint32_t (*__restrict__ As)[20], const uint32_t (*__restrict__ Bs)[132],
    int warp_m, int warp_n, int g, int tig, float c[2][8][4])
{
    #pragma unroll
    for (int kk = 0; kk < 16; kk += 8) {
        uint32_t a[2][4];
        #pragma unroll
        for (int mf = 0; mf < 2; mf++) {
            int rb = warp_m * 32 + mf * 16;
            a[mf][0] = As[rb + g][kk + tig];
            a[mf][1] = As[rb + g + 8][kk + tig];
            a[mf][2] = As[rb + g][kk + tig + 4];
            a[mf][3] = As[rb + g + 8][kk + tig + 4];
        }
        #pragma unroll
        for (int nf = 0; nf < 8; nf++) {
            int cb = warp_n * 64 + nf * 8 + g;
            uint32_t b[2];
            b[0] = Bs[kk + tig][cb];
            b[1] = Bs[kk + tig + 4][cb];
            mma8(c[0][nf], a[0], b);
            mma8(c[1][nf], a[1], b);
        }
    }
}

// ===========================================================================
// GEMM1/GEMM2 (R3-verbatim).
// ===========================================================================
template <int MODE>
__global__ __launch_bounds__(256)
void gemm_lrelu_tc(const float* __restrict__ Ain,
                   const float* __restrict__ W,
                   const float* __restrict__ bias)
{
    __shared__ uint32_t As[128][20];
    __shared__ uint32_t Bs[16][132];

    const int tid    = threadIdx.x;
    const int wid    = tid >> 5;
    const int lane   = tid & 31;
    const int g      = lane >> 2;
    const int tig    = lane & 3;
    const int warp_m = wid >> 1;
    const int warp_n = wid & 1;
    const int row0   = blockIdx.x * 128;
    const int col0   = blockIdx.y * 128;

    const float* A = (MODE == 0) ? Ain : g_S1;
    float*       C = (MODE == 0) ? g_S1 : g_Sh;

    float c[2][8][4];
    #pragma unroll
    for (int i = 0; i < 2; i++)
        #pragma unroll
        for (int j = 0; j < 8; j++)
            #pragma unroll
            for (int q = 0; q < 4; q++) c[i][j][q] = 0.f;

    for (int k0 = 0; k0 < DD; k0 += 16) {
        if (MODE == 0) {
            #pragma unroll
            for (int i = 0; i < 8; i++) {
                int e = tid + i * 256;
                int r = e >> 4, k = e & 15;
                int gr = row0 + r;
                int b  = gr >> 4, nn = gr & 15;
                As[r][k] = f2tf32(A[(size_t)b * (DD * NN) + (size_t)(k0 + k) * NN + nn]);
            }
        } else {
            #pragma unroll
            for (int i = 0; i < 2; i++) {
                int e = tid + i * 256;
                int r = e >> 2, c4 = e & 3;
                float4 v = *reinterpret_cast<const float4*>(
                    &A[(size_t)(row0 + r) * DD + k0 + c4 * 4]);
                As[r][c4 * 4 + 0] = f2tf32(v.x);
                As[r][c4 * 4 + 1] = f2tf32(v.y);
                As[r][c4 * 4 + 2] = f2tf32(v.z);
                As[r][c4 * 4 + 3] = f2tf32(v.w);
            }
        }
        #pragma unroll
        for (int i = 0; i < 2; i++) {
            int e = tid + i * 256;
            int k = e >> 5, c4 = e & 31;
            float4 v = *reinterpret_cast<const float4*>(
                &W[(size_t)(k0 + k) * DD + col0 + c4 * 4]);
            Bs[k][c4 * 4 + 0] = f2tf32(v.x);
            Bs[k][c4 * 4 + 1] = f2tf32(v.y);
            Bs[k][c4 * 4 + 2] = f2tf32(v.z);
            Bs[k][c4 * 4 + 3] = f2tf32(v.w);
        }
        __syncthreads();
        warp_mma_chunk(As, Bs, warp_m, warp_n, g, tig, c);
        __syncthreads();
    }

    #pragma unroll
    for (int mf = 0; mf < 2; mf++) {
        #pragma unroll
        for (int half = 0; half < 2; half++) {
            int r = row0 + warp_m * 32 + mf * 16 + g + half * 8;
            size_t orow = (MODE == 0) ? (size_t)r
                                      : (size_t)((r & 15) * 1024 + (r >> 4));
            #pragma unroll
            for (int nf = 0; nf < 8; nf++) {
                int col = col0 + warp_n * 64 + nf * 8 + 2 * tig;
                float2 v;
                v.x = lrelu(c[mf][nf][half * 2 + 0] + bias[col]);
                v.y = lrelu(c[mf][nf][half * 2 + 1] + bias[col + 1]);
                *reinterpret_cast<float2*>(&C[orow * DD + col]) = v;
            }
        }
    }
}

// ===========================================================================
// Prep: relayout g_Sh / Wc1 into slotted fragment order (inverse of R8 maps).
// A slot (mgroup=slot>>2, cc=slot&3), intra idx = t*4+j:
//   r = mgroup*16 + (j&1)*8 + t/4 ; k_local = cc*8 + (j>>1)*4 + t%4
// B slot (cc=slot>>3, wn=(slot>>2)&1, np=slot&3), intra idx = t*4+j:
//   nn = wn*64 + np*16 + (j>>1)*8 + t/4 ; kl = cc*8 + (j&1)*4 + t%4
// ===========================================================================
__global__ __launch_bounds__(256)
void prep_slotA_kernel()
{
    int e = blockIdx.x * 256 + threadIdx.x;        // < 8388608
    int i128 = e & 127, slot = (e >> 7) & 31, kc = (e >> 12) & 15, tile = e >> 16;
    int mg = slot >> 2, cc = slot & 3;
    int t = i128 >> 2, j = i128 & 3;
    int r  = mg * 16 + ((j & 1) << 3) + (t >> 2);
    int kl = cc * 8 + (((j >> 1) & 1) << 2) + (t & 3);
    g_A[e] = f2tf32(g_Sh[(size_t)(tile * 128 + r) * DD + kc * 32 + kl]);
}

__global__ __launch_bounds__(256)
void prep_slotB_kernel(const float* __restrict__ Wc1)
{
    int e = blockIdx.x * 256 + threadIdx.x;        // < 4194304
    int i128 = e & 127, slot = (e >> 7) & 31, kc = (e >> 12) & 15;
    int hb = (e >> 16) & 3, n = e >> 18;
    int cc = slot >> 3, wn = (slot >> 2) & 1, np = slot & 3;
    int t = i128 >> 2, j = i128 & 3;
    int nn = wn * 64 + np * 16 + (((j >> 1) & 1) << 3) + (t >> 2);
    int kl = cc * 8 + ((j & 1) << 2) + (t & 3);
    g_B[e] = f2tf32(Wc1[(size_t)n * DD * HH + (size_t)(kc * 32 + kl) * HH
                        + hb * 128 + nn]);
}

// ===========================================================================
// GEMM3: consumes pre-slotted g_A/g_B via contiguous cp.async.cg copies,
// double-buffered. mma loop + epilogue byte-identical to R8.
// smem: A0,A1,B0,B1 each 32 slots * 128 u32 = 16KB -> 64KB dynamic.
// ===========================================================================
#define SLOTU 128
#define BUFU  4096          // u32 per buffer (32*128)
#define G3_SMEM 65536

__global__ __launch_bounds__(128)
void gemm_head_tc(const float* __restrict__ bc1,
                  const float* __restrict__ Wc2,
                  float* __restrict__ logits)
{
    extern __shared__ uint32_t sm[];
    uint32_t* Ab[2] = {sm, sm + BUFU};
    uint32_t* Bb[2] = {sm + 2 * BUFU, sm + 3 * BUFU};

    const int tid  = threadIdx.x;       // 128 threads, 4 warps
    const int wid  = tid >> 5;
    const int lane = tid & 31;
    const int g    = lane >> 2;
    const int tig  = lane & 3;
    const int wm   = wid >> 1;
    const int wn   = wid & 1;
    const int tile = blockIdx.x;
    const int hb   = blockIdx.y;
    const int n    = blockIdx.z;
    const int row0 = tile * 128;
    const int h0   = hb * 128;

    const uint32_t* __restrict__ srcA = g_A + (size_t)tile * 16 * BUFU;
    const uint32_t* __restrict__ srcB = g_B + (size_t)(n * 4 + hb) * 16 * BUFU;

    float c[4][8][4];
    #pragma unroll
    for (int i = 0; i < 4; i++)
        #pragma unroll
        for (int j = 0; j < 8; j++)
            #pragma unroll
            for (int q = 0; q < 4; q++) c[i][j][q] = 0.f;

    auto stage = [&](int kc) {
        const int buf = kc & 1;
        const uint32_t* sa = srcA + kc * BUFU;
        const uint32_t* sb = srcB + kc * BUFU;
        uint32_t da = smem_u32(Ab[buf]);
        uint32_t db = smem_u32(Bb[buf]);
        #pragma unroll
        for (int i = 0; i < 8; i++) {
            int ch = tid + i * 128;                 // 0..1023 16B-chunks
            cpcg16(da + ch * 16, sa + ch * 4);
            cpcg16(db + ch * 16, sb + ch * 4);
        }
        cp_commit();
    };

    stage(0);
    stage(1);
    for (int kc = 0; kc < 16; kc++) {
        if (kc < 15) cp_wait<1>(); else cp_wait<0>();
        __syncthreads();
        const uint32_t* Asl = Ab[kc & 1];
        const uint32_t* Bsl = Bb[kc & 1];
        #pragma unroll
        for (int cc = 0; cc < 4; cc++) {
            uint4 af[4];
            #pragma unroll
            for (int mf = 0; mf < 4; mf++)
                af[mf] = *reinterpret_cast<const uint4*>(
                    &Asl[((wm * 4 + mf) * 4 + cc) * SLOTU + lane * 4]);
            uint4 bf[4];
            #pragma unroll
            for (int np = 0; np < 4; np++)
                bf[np] = *reinterpret_cast<const uint4*>(
                    &Bsl[((cc * 2 + wn) * 4 + np) * SLOTU + lane * 4]);
            #pragma unroll
            for (int np = 0; np < 4; np++) {
                const uint32_t* bb = reinterpret_cast<const uint32_t*>(&bf[np]);
                #pragma unroll
                for (int mf = 0; mf < 4; mf++) {
                    const uint32_t* aa = reinterpret_cast<const uint32_t*>(&af[mf]);
                    mma8(c[mf][2 * np + 0], aa, bb);
                    mma8(c[mf][2 * np + 1], aa, bb + 2);
                }
            }
        }
        __syncthreads();
        if (kc + 2 < 16) stage(kc + 2);
    }

    // --- fused epilogue (R8-verbatim): lrelu(+bc1)*Wc2, shfl reduce, atomicAdd ---
    float p[8];
    #pragma unroll
    for (int i = 0; i < 8; i++) p[i] = 0.f;
    #pragma unroll
    for (int nf = 0; nf < 8; nf++) {
        int h = h0 + wn * 64 + nf * 8 + 2 * tig;
        float b1a = bc1[n * HH + h],     b1b = bc1[n * HH + h + 1];
        float w2a = Wc2[n * HH + h],     w2b = Wc2[n * HH + h + 1];
        #pragma unroll
        for (int mf = 0; mf < 4; mf++) {
            p[2 * mf + 0] += lrelu(c[mf][nf][0] + b1a) * w2a
                           + lrelu(c[mf][nf][1] + b1b) * w2b;
            p[2 * mf + 1] += lrelu(c[mf][nf][2] + b1a) * w2a
                           + lrelu(c[mf][nf][3] + b1b) * w2b;
        }
    }
    #pragma unroll
    for (int i = 0; i < 8; i++) {
        float v = p[i];
        v += __shfl_xor_sync(0xffffffffu, v, 1);
        v += __shfl_xor_sync(0xffffffffu, v, 2);
        if (tig == 0) {
            int mf = i >> 1, half = i & 1;
            int r = row0 + wm * 64 + mf * 16 + g + half * 8;
            atomicAdd(&logits[r * NN + n], v);
        }
    }
}

__global__ void zero_kernel(float* __restrict__ p, int n)
{
    int i = blockIdx.x * 256 + threadIdx.x;
    if (i < n) p[i] = 0.f;
}

// full_out += bc2; out[b,n] = sigmoid(diagonal of full_out)  (R3-verbatim)
__global__ void finalize_kernel(float* __restrict__ out,
                                const float* __restrict__ bc2)
{
    int idx = blockIdx.x * 256 + threadIdx.x;      // < 262144
    int m = idx >> 4, n = idx & 15;
    float* full = out + MTOT;
    float v = full[idx] + bc2[n];
    full[idx] = v;
    if ((m >> 10) == n) {                           // m = n*1024 + b
        int b = m & 1023;
        out[b * NN + n] = 1.f / (1.f + expf(-v));
    }
}

extern "C" void kernel_launch(void* const* d_in, const int* in_sizes, int n_in,
                              void* d_out, int out_size)
{
    const float* x   = (const float*)d_in[0];
    const float* Ws1 = (const float*)d_in[1];
    const float* bs1 = (const float*)d_in[2];
    const float* Ws2 = (const float*)d_in[3];
    const float* bs2 = (const float*)d_in[4];
    const float* Wc1 = (const float*)d_in[5];
    const float* bc1 = (const float*)d_in[6];
    const float* Wc2 = (const float*)d_in[7];
    const float* bc2 = (const float*)d_in[8];
    float* out = (float*)d_out;

    cudaFuncSetAttribute(gemm_head_tc,
                         cudaFuncAttributeMaxDynamicSharedMemorySize, G3_SMEM);

    dim3 blk(256);
    gemm_lrelu_tc<0><<<dim3(MTOT / 128, DD / 128), blk>>>(x, Ws1, bs1);
    gemm_lrelu_tc<1><<<dim3(MTOT / 128, DD / 128), blk>>>(nullptr, Ws2, bs2);
    // prep: slot-format A (from g_Sh) and B (from Wc1); B can run early
    prep_slotB_kernel<<<4194304 / 256, blk>>>(Wc1);
    prep_slotA_kernel<<<8388608 / 256, blk>>>();
    zero_kernel<<<(MTOT * NN + 255) / 256, blk>>>(out + MTOT, MTOT * NN);
    gemm_head_tc<<<dim3(128, 4, NN), dim3(128), G3_SMEM>>>(bc1, Wc2, out + MTOT);
    finalize_kernel<<<(MTOT * NN + 255) / 256, blk>>>(out, bc2);
}

// round 10
// speedup vs baseline: 5.3326x; 1.4519x over previous
#include <cuda_runtime.h>
#include <cuda_fp16.h>
#include <math.h>
#include <stdint.h>

// B=1024, D=512, N=16, H=512, M = N*B = 16384
#define DD   512
#define NN   16
#define HH   512
#define MTOT 16384

// Scratch (static __device__ — no allocations allowed)
__device__ float g_S1[MTOT * DD];   // lrelu(xT @ Ws1 + bs1), rows r = b*16+n
__device__ float g_Sh[MTOT * DD];   // shared, PERMUTED rows: m = n*1024 + b
// Pre-slotted fp16 operands for GEMM3 (u32 = packed half2):
//   g_Ah[tile(128)][kc(16)][slot(16)][128]  from g_Sh
//   g_Bh[n*4+hb(64)][kc(16)][slot(16)][128] from Wc1
__device__ uint32_t g_Ah[128 * 16 * 16 * 128];
__device__ uint32_t g_Bh[64  * 16 * 16 * 128];

__device__ __forceinline__ float lrelu(float v) { return v >= 0.f ? v : 0.1f * v; }

__device__ __forceinline__ uint32_t f2tf32(float f) {
    uint32_t u;
    asm("cvt.rna.tf32.f32 %0, %1;" : "=r"(u) : "f"(f));
    return u;
}
__device__ __forceinline__ uint32_t pack_h2(float lo, float hi) {
    __half2 h = __floats2half2_rn(lo, hi);
    return *reinterpret_cast<uint32_t*>(&h);
}
__device__ __forceinline__ uint32_t smem_u32(const void* p) {
    uint32_t a;
    asm("{ .reg .u64 t; cvta.to.shared.u64 t, %1; cvt.u32.u64 %0, t; }" : "=r"(a) : "l"(p));
    return a;
}
__device__ __forceinline__ void cpcg16(uint32_t dst, const void* src) {
    asm volatile("cp.async.cg.shared.global [%0], [%1], 16;" :: "r"(dst), "l"(src));
}
__device__ __forceinline__ void cp_commit() {
    asm volatile("cp.async.commit_group;" ::: "memory");
}
template <int N>
__device__ __forceinline__ void cp_wait() {
    asm volatile("cp.async.wait_group %0;" :: "n"(N) : "memory");
}

__device__ __forceinline__ void mma8(float* c, const uint32_t* a, const uint32_t* b) {
    asm volatile(
        "mma.sync.aligned.m16n8k8.row.col.f32.tf32.tf32.f32 "
        "{%0,%1,%2,%3}, {%4,%5,%6,%7}, {%8,%9}, {%0,%1,%2,%3};"
        : "+f"(c[0]), "+f"(c[1]), "+f"(c[2]), "+f"(c[3])
        : "r"(a[0]), "r"(a[1]), "r"(a[2]), "r"(a[3]), "r"(b[0]), "r"(b[1]));
}
__device__ __forceinline__ void mma16h(float* c, const uint32_t* a,
                                       uint32_t b0, uint32_t b1) {
    asm volatile(
        "mma.sync.aligned.m16n8k16.row.col.f32.f16.f16.f32 "
        "{%0,%1,%2,%3}, {%4,%5,%6,%7}, {%8,%9}, {%0,%1,%2,%3};"
        : "+f"(c[0]), "+f"(c[1]), "+f"(c[2]), "+f"(c[3])
        : "r"(a[0]), "r"(a[1]), "r"(a[2]), "r"(a[3]), "r"(b0), "r"(b1));
}

// Shared warp-level MMA over one staged k16 chunk (R3-verbatim, for GEMM1/2).
__device__ __forceinline__ void warp_mma_chunk(
    const uint32_t (*__restrict__ As)[20], const uint32_t (*__restrict__ Bs)[132],
    int warp_m, int warp_n, int g, int tig, float c[2][8][4])
{
    #pragma unroll
    for (int kk = 0; kk < 16; kk += 8) {
        uint32_t a[2][4];
        #pragma unroll
        for (int mf = 0; mf < 2; mf++) {
            int rb = warp_m * 32 + mf * 16;
            a[mf][0] = As[rb + g][kk + tig];
            a[mf][1] = As[rb + g + 8][kk + tig];
            a[mf][2] = As[rb + g][kk + tig + 4];
            a[mf][3] = As[rb + g + 8][kk + tig + 4];
        }
        #pragma unroll
        for (int nf = 0; nf < 8; nf++) {
            int cb = warp_n * 64 + nf * 8 + g;
            uint32_t b[2];
            b[0] = Bs[kk + tig][cb];
            b[1] = Bs[kk + tig + 4][cb];
            mma8(c[0][nf], a[0], b);
            mma8(c[1][nf], a[1], b);
        }
    }
}

// ===========================================================================
// GEMM1/GEMM2 (R3-verbatim).
// ===========================================================================
template <int MODE>
__global__ __launch_bounds__(256)
void gemm_lrelu_tc(const float* __restrict__ Ain,
                   const float* __restrict__ W,
                   const float* __restrict__ bias)
{
    __shared__ uint32_t As[128][20];
    __shared__ uint32_t Bs[16][132];

    const int tid    = threadIdx.x;
    const int wid    = tid >> 5;
    const int lane   = tid & 31;
    const int g      = lane >> 2;
    const int tig    = lane & 3;
    const int warp_m = wid >> 1;
    const int warp_n = wid & 1;
    const int row0   = blockIdx.x * 128;
    const int col0   = blockIdx.y * 128;

    const float* A = (MODE == 0) ? Ain : g_S1;
    float*       C = (MODE == 0) ? g_S1 : g_Sh;

    float c[2][8][4];
    #pragma unroll
    for (int i = 0; i < 2; i++)
        #pragma unroll
        for (int j = 0; j < 8; j++)
            #pragma unroll
            for (int q = 0; q < 4; q++) c[i][j][q] = 0.f;

    for (int k0 = 0; k0 < DD; k0 += 16) {
        if (MODE == 0) {
            #pragma unroll
            for (int i = 0; i < 8; i++) {
                int e = tid + i * 256;
                int r = e >> 4, k = e & 15;
                int gr = row0 + r;
                int b  = gr >> 4, nn = gr & 15;
                As[r][k] = f2tf32(A[(size_t)b * (DD * NN) + (size_t)(k0 + k) * NN + nn]);
            }
        } else {
            #pragma unroll
            for (int i = 0; i < 2; i++) {
                int e = tid + i * 256;
                int r = e >> 2, c4 = e & 3;
                float4 v = *reinterpret_cast<const float4*>(
                    &A[(size_t)(row0 + r) * DD + k0 + c4 * 4]);
                As[r][c4 * 4 + 0] = f2tf32(v.x);
                As[r][c4 * 4 + 1] = f2tf32(v.y);
                As[r][c4 * 4 + 2] = f2tf32(v.z);
                As[r][c4 * 4 + 3] = f2tf32(v.w);
            }
        }
        #pragma unroll
        for (int i = 0; i < 2; i++) {
            int e = tid + i * 256;
            int k = e >> 5, c4 = e & 31;
            float4 v = *reinterpret_cast<const float4*>(
                &W[(size_t)(k0 + k) * DD + col0 + c4 * 4]);
            Bs[k][c4 * 4 + 0] = f2tf32(v.x);
            Bs[k][c4 * 4 + 1] = f2tf32(v.y);
            Bs[k][c4 * 4 + 2] = f2tf32(v.z);
            Bs[k][c4 * 4 + 3] = f2tf32(v.w);
        }
        __syncthreads();
        warp_mma_chunk(As, Bs, warp_m, warp_n, g, tig, c);
        __syncthreads();
    }

    #pragma unroll
    for (int mf = 0; mf < 2; mf++) {
        #pragma unroll
        for (int half = 0; half < 2; half++) {
            int r = row0 + warp_m * 32 + mf * 16 + g + half * 8;
            size_t orow = (MODE == 0) ? (size_t)r
                                      : (size_t)((r & 15) * 1024 + (r >> 4));
            #pragma unroll
            for (int nf = 0; nf < 8; nf++) {
                int col = col0 + warp_n * 64 + nf * 8 + 2 * tig;
                float2 v;
                v.x = lrelu(c[mf][nf][half * 2 + 0] + bias[col]);
                v.y = lrelu(c[mf][nf][half * 2 + 1] + bias[col + 1]);
                *reinterpret_cast<float2*>(&C[orow * DD + col]) = v;
            }
        }
    }
}

// ===========================================================================
// Prep: slot-format fp16 fragments for m16n8k16.
// A slot s = mf*2+ks (mf: 16-row group 0..7, ks: k16 half of the k32 chunk).
//   intra i128 = t*4+j: r = mf*16 + ((j&1)<<3) + t/4 ;
//                       k = ks*16 + ((j>>1)<<3) + 2*(t%4)   (half2: k, k+1)
// B slot s = n16*2+ks (n16: 16-col group 0..7).
//   intra: n = n16*16 + ((j>>1)<<3) + t/4 ;
//          k = ks*16 + ((j&1)<<3) + 2*(t%4)                 (half2: k, k+1)
// ===========================================================================
__global__ __launch_bounds__(256)
void prep_slotA_kernel()
{
    int e = blockIdx.x * 256 + threadIdx.x;        // < 4194304
    int i128 = e & 127, s = (e >> 7) & 15, kc = (e >> 11) & 15, tile = e >> 15;
    int mf = s >> 1, ks = s & 1;
    int t = i128 >> 2, j = i128 & 3;
    int r  = mf * 16 + ((j & 1) << 3) + (t >> 2);
    int k  = kc * 32 + ks * 16 + (((j >> 1) & 1) << 3) + 2 * (t & 3);
    const float* row = &g_Sh[(size_t)(tile * 128 + r) * DD];
    g_Ah[e] = pack_h2(row[k], row[k + 1]);
}

__global__ __launch_bounds__(256)
void prep_slotB_kernel(const float* __restrict__ Wc1)
{
    int e = blockIdx.x * 256 + threadIdx.x;        // < 2097152
    int i128 = e & 127, s = (e >> 7) & 15, kc = (e >> 11) & 15;
    int hb = (e >> 15) & 3, n = e >> 17;
    int n16 = s >> 1, ks = s & 1;
    int t = i128 >> 2, j = i128 & 3;
    int nc = hb * 128 + n16 * 16 + (((j >> 1) & 1) << 3) + (t >> 2);
    int k  = kc * 32 + ks * 16 + ((j & 1) << 3) + 2 * (t & 3);
    const float* W = Wc1 + (size_t)n * DD * HH;
    g_Bh[e] = pack_h2(W[(size_t)k * HH + nc], W[(size_t)(k + 1) * HH + nc]);
}

// ===========================================================================
// GEMM3: fp16 m16n8k16, pre-slotted operands, 3-stage cp.async pipeline.
// 4 warps of 64x64 tiles. Epilogue identical to R9 (lrelu(+bc1)*Wc2, shfl
// reduce, atomicAdd into logits).
// smem: 3 x (A 8KB + B 8KB) = 48KB.
// ===========================================================================
#define SLOTU 128
#define BUFU  2048          // u32 per buffer (16 slots * 128)
#define G3_SMEM 49152

__global__ __launch_bounds__(128)
void gemm_head_tc(const float* __restrict__ bc1,
                  const float* __restrict__ Wc2,
                  float* __restrict__ logits)
{
    extern __shared__ uint32_t sm[];
    uint32_t* Ab[3] = {sm, sm + BUFU, sm + 2 * BUFU};
    uint32_t* Bb[3] = {sm + 3 * BUFU, sm + 4 * BUFU, sm + 5 * BUFU};

    const int tid  = threadIdx.x;       // 128 threads, 4 warps
    const int wid  = tid >> 5;
    const int lane = tid & 31;
    const int g    = lane >> 2;
    const int tig  = lane & 3;
    const int wm   = wid >> 1;
    const int wn   = wid & 1;
    const int tile = blockIdx.x;
    const int hb   = blockIdx.y;
    const int n    = blockIdx.z;
    const int row0 = tile * 128;
    const int h0   = hb * 128;

    const uint32_t* __restrict__ srcA = g_Ah + (size_t)tile * 16 * BUFU;
    const uint32_t* __restrict__ srcB = g_Bh + (size_t)(n * 4 + hb) * 16 * BUFU;

    float c[4][8][4];
    #pragma unroll
    for (int i = 0; i < 4; i++)
        #pragma unroll
        for (int j = 0; j < 8; j++)
            #pragma unroll
            for (int q = 0; q < 4; q++) c[i][j][q] = 0.f;

    auto stage = [&](int kc) {
        const int buf = kc % 3;
        const uint32_t* sa = srcA + kc * BUFU;
        const uint32_t* sb = srcB + kc * BUFU;
        uint32_t da = smem_u32(Ab[buf]);
        uint32_t db = smem_u32(Bb[buf]);
        #pragma unroll
        for (int i = 0; i < 4; i++) {
            int ch = tid + i * 128;                 // 0..511 16B-chunks
            cpcg16(da + ch * 16, sa + ch * 4);
            cpcg16(db + ch * 16, sb + ch * 4);
        }
        cp_commit();
    };

    stage(0);
    stage(1);
    stage(2);
    for (int kc = 0; kc < 16; kc++) {
        if (kc <= 12)      cp_wait<2>();
        else if (kc == 13) cp_wait<2>();
        else if (kc == 14) cp_wait<1>();
        else               cp_wait<0>();
        __syncthreads();
        const uint32_t* Asl = Ab[kc % 3];
        const uint32_t* Bsl = Bb[kc % 3];
        #pragma unroll
        for (int ks = 0; ks < 2; ks++) {
            uint4 af[4];
            #pragma unroll
            for (int mfl = 0; mfl < 4; mfl++)
                af[mfl] = *reinterpret_cast<const uint4*>(
                    &Asl[((wm * 4 + mfl) * 2 + ks) * SLOTU + lane * 4]);
            uint4 bf[4];
            #pragma unroll
            for (int np = 0; np < 4; np++)
                bf[np] = *reinterpret_cast<const uint4*>(
                    &Bsl[((wn * 4 + np) * 2 + ks) * SLOTU + lane * 4]);
            #pragma unroll
            for (int np = 0; np < 4; np++) {
                #pragma unroll
                for (int mfl = 0; mfl < 4; mfl++) {
                    const uint32_t* aa = reinterpret_cast<const uint32_t*>(&af[mfl]);
                    mma16h(c[mfl][2 * np + 0], aa, bf[np].x, bf[np].y);
                    mma16h(c[mfl][2 * np + 1], aa, bf[np].z, bf[np].w);
                }
            }
        }
        __syncthreads();
        if (kc + 3 < 16) stage(kc + 3);
    }

    // --- fused epilogue (R9-verbatim): lrelu(+bc1)*Wc2, shfl reduce, atomicAdd ---
    float p[8];
    #pragma unroll
    for (int i = 0; i < 8; i++) p[i] = 0.f;
    #pragma unroll
    for (int nf = 0; nf < 8; nf++) {
        int h = h0 + wn * 64 + nf * 8 + 2 * tig;
        float b1a = bc1[n * HH + h],     b1b = bc1[n * HH + h + 1];
        float w2a = Wc2[n * HH + h],     w2b = Wc2[n * HH + h + 1];
        #pragma unroll
        for (int mf = 0; mf < 4; mf++) {
            p[2 * mf + 0] += lrelu(c[mf][nf][0] + b1a) * w2a
                           + lrelu(c[mf][nf][1] + b1b) * w2b;
            p[2 * mf + 1] += lrelu(c[mf][nf][2] + b1a) * w2a
                           + lrelu(c[mf][nf][3] + b1b) * w2b;
        }
    }
    #pragma unroll
    for (int i = 0; i < 8; i++) {
        float v = p[i];
        v += __shfl_xor_sync(0xffffffffu, v, 1);
        v += __shfl_xor_sync(0xffffffffu, v, 2);
        if (tig == 0) {
            int mf = i >> 1, half = i & 1;
            int r = row0 + wm * 64 + mf * 16 + g + half * 8;
            atomicAdd(&logits[r * NN + n], v);
        }
    }
}

__global__ void zero_kernel(float* __restrict__ p, int n)
{
    int i = blockIdx.x * 256 + threadIdx.x;
    if (i < n) p[i] = 0.f;
}

// full_out += bc2; out[b,n] = sigmoid(diagonal of full_out)  (R3-verbatim)
__global__ void finalize_kernel(float* __restrict__ out,
                                const float* __restrict__ bc2)
{
    int idx = blockIdx.x * 256 + threadIdx.x;      // < 262144
    int m = idx >> 4, n = idx & 15;
    float* full = out + MTOT;
    float v = full[idx] + bc2[n];
    full[idx] = v;
    if ((m >> 10) == n) {                           // m = n*1024 + b
        int b = m & 1023;
        out[b * NN + n] = 1.f / (1.f + expf(-v));
    }
}

extern "C" void kernel_launch(void* const* d_in, const int* in_sizes, int n_in,
                              void* d_out, int out_size)
{
    const float* x   = (const float*)d_in[0];
    const float* Ws1 = (const float*)d_in[1];
    const float* bs1 = (const float*)d_in[2];
    const float* Ws2 = (const float*)d_in[3];
    const float* bs2 = (const float*)d_in[4];
    const float* Wc1 = (const float*)d_in[5];
    const float* bc1 = (const float*)d_in[6];
    const float* Wc2 = (const float*)d_in[7];
    const float* bc2 = (const float*)d_in[8];
    float* out = (float*)d_out;

    cudaFuncSetAttribute(gemm_head_tc,
                         cudaFuncAttributeMaxDynamicSharedMemorySize, G3_SMEM);

    dim3 blk(256);
    gemm_lrelu_tc<0><<<dim3(MTOT / 128, DD / 128), blk>>>(x, Ws1, bs1);
    gemm_lrelu_tc<1><<<dim3(MTOT / 128, DD / 128), blk>>>(nullptr, Ws2, bs2);
    // prep: slot-format B (from Wc1, independent) and A (from g_Sh)
    prep_slotB_kernel<<<2097152 / 256, blk>>>(Wc1);
    prep_slotA_kernel<<<4194304 / 256, blk>>>();
    zero_kernel<<<(MTOT * NN + 255) / 256, blk>>>(out + MTOT, MTOT * NN);
    gemm_head_tc<<<dim3(128, 4, NN), dim3(128), G3_SMEM>>>(bc1, Wc2, out + MTOT);
    finalize_kernel<<<(MTOT * NN + 255) / 256, blk>>>(out, bc2);
}

// round 11
// speedup vs baseline: 6.6973x; 1.2559x over previous
#include <cuda_runtime.h>
#include <cuda_fp16.h>
#include <math.h>
#include <stdint.h>

// B=1024, D=512, N=16, H=512, M = N*B = 16384
#define DD   512
#define NN   16
#define HH   512
#define MTOT 16384

// Slotted fp16 fragment files (u32 = packed half2).
// A files: [tile(128)][kc(16)][slot(16)][128]; slot = mf*2+ks.
// B files: [blk][kc(16)][slot(16)][128];     slot = n16*2+ks.
__device__ uint32_t g_A1[128 * 16 * 16 * 128];   // x (gathered), GEMM1 A
__device__ uint32_t g_A2[128 * 16 * 16 * 128];   // lrelu(X@Ws1+bs1), GEMM2 A
__device__ uint32_t g_A3[128 * 16 * 16 * 128];   // shared, GEMM3 A (r-ordered)
__device__ uint32_t g_WB1[4  * 16 * 16 * 128];   // Ws1 slotted
__device__ uint32_t g_WB2[4  * 16 * 16 * 128];   // Ws2 slotted
__device__ uint32_t g_Bh [64 * 16 * 16 * 128];   // Wc1 slotted [n*4+hb]

__device__ __forceinline__ float lrelu(float v) { return v >= 0.f ? v : 0.1f * v; }
__device__ __forceinline__ uint32_t pack_h2(float lo, float hi) {
    __half2 h = __floats2half2_rn(lo, hi);
    return *reinterpret_cast<uint32_t*>(&h);
}
__device__ __forceinline__ uint32_t smem_u32(const void* p) {
    uint32_t a;
    asm("{ .reg .u64 t; cvta.to.shared.u64 t, %1; cvt.u32.u64 %0, t; }" : "=r"(a) : "l"(p));
    return a;
}
__device__ __forceinline__ void cpcg16(uint32_t dst, const void* src) {
    asm volatile("cp.async.cg.shared.global [%0], [%1], 16;" :: "r"(dst), "l"(src));
}
__device__ __forceinline__ void cp_commit() {
    asm volatile("cp.async.commit_group;" ::: "memory");
}
template <int N>
__device__ __forceinline__ void cp_wait() {
    asm volatile("cp.async.wait_group %0;" :: "n"(N) : "memory");
}
__device__ __forceinline__ void mma16h(float* c, const uint32_t* a,
                                       uint32_t b0, uint32_t b1) {
    asm volatile(
        "mma.sync.aligned.m16n8k16.row.col.f32.f16.f16.f32 "
        "{%0,%1,%2,%3}, {%4,%5,%6,%7}, {%8,%9}, {%0,%1,%2,%3};"
        : "+f"(c[0]), "+f"(c[1]), "+f"(c[2]), "+f"(c[3])
        : "r"(a[0]), "r"(a[1]), "r"(a[2]), "r"(a[3]), "r"(b0), "r"(b1));
}

#define SLOTU 128
#define BUFU  2048          // u32 per (kc) buffer: 16 slots * 128
#define G3_SMEM 49152       // 3 stages x (A 8KB + B 8KB)

// ===========================================================================
// Prep kernels.
// A slot map (R10-proven): slot s = mf*2+ks; i128 = t*4+j:
//   r = mf*16 + ((j&1)<<3) + t/4 ; k = kc*32 + ks*16 + ((j>>1)<<3) + 2*(t%4)
// B slot map: s = n16*2+ks; i128 = t*4+j:
//   nc = n16*16 + ((j>>1)<<3) + t/4 ; k = kc*32 + ks*16 + ((j&1)<<3) + 2*(t%4)
// ===========================================================================
// x (B,D,N) -> g_A1 (rows r = b*16+n)
__global__ __launch_bounds__(256)
void prep_xA_kernel(const float* __restrict__ x)
{
    int e = blockIdx.x * 256 + threadIdx.x;        // < 4194304
    int i128 = e & 127, s = (e >> 7) & 15, kc = (e >> 11) & 15, tile = e >> 15;
    int mf = s >> 1, ks = s & 1;
    int t = i128 >> 2, j = i128 & 3;
    int r = tile * 128 + mf * 16 + ((j & 1) << 3) + (t >> 2);
    int k = kc * 32 + ks * 16 + (((j >> 1) & 1) << 3) + 2 * (t & 3);
    const float* xb = x + (size_t)(r >> 4) * (DD * NN) + (r & 15);
    g_A1[e] = pack_h2(xb[(size_t)k * NN], xb[(size_t)(k + 1) * NN]);
}

// W [512][512] row-major -> slotted B
__global__ __launch_bounds__(256)
void prep_wB_kernel(const float* __restrict__ W, uint32_t* __restrict__ dst)
{
    int e = blockIdx.x * 256 + threadIdx.x;        // < 131072
    int i128 = e & 127, s = (e >> 7) & 15, kc = (e >> 11) & 15, hb = e >> 15;
    int n16 = s >> 1, ks = s & 1;
    int t = i128 >> 2, j = i128 & 3;
    int nc = hb * 128 + n16 * 16 + (((j >> 1) & 1) << 3) + (t >> 2);
    int k  = kc * 32 + ks * 16 + ((j & 1) << 3) + 2 * (t & 3);
    dst[e] = pack_h2(W[(size_t)k * DD + nc], W[(size_t)(k + 1) * DD + nc]);
}

// Wc1 [n][K][H] -> g_Bh (R10-verbatim)
__global__ __launch_bounds__(256)
void prep_slotB_kernel(const float* __restrict__ Wc1)
{
    int e = blockIdx.x * 256 + threadIdx.x;        // < 2097152
    int i128 = e & 127, s = (e >> 7) & 15, kc = (e >> 11) & 15;
    int hb = (e >> 15) & 3, n = e >> 17;
    int n16 = s >> 1, ks = s & 1;
    int t = i128 >> 2, j = i128 & 3;
    int nc = hb * 128 + n16 * 16 + (((j >> 1) & 1) << 3) + (t >> 2);
    int k  = kc * 32 + ks * 16 + ((j & 1) << 3) + 2 * (t & 3);
    const float* W = Wc1 + (size_t)n * DD * HH;
    g_Bh[e] = pack_h2(W[(size_t)k * HH + nc], W[(size_t)(k + 1) * HH + nc]);
}

// ===========================================================================
// Shared mainloop: 3-stage cp.async pipeline + fp16 m16n8k16, 4 warps 64x64.
// (R10 gemm_head_tc core, verbatim.)
// ===========================================================================
struct Core {
    const uint32_t* srcA;
    const uint32_t* srcB;
    uint32_t* Ab[3];
    uint32_t* Bb[3];
    int tid, lane, wm, wn;

    __device__ __forceinline__ void stage(int kc) {
        const int buf = kc % 3;
        const uint32_t* sa = srcA + kc * BUFU;
        const uint32_t* sb = srcB + kc * BUFU;
        uint32_t da = smem_u32(Ab[buf]);
        uint32_t db = smem_u32(Bb[buf]);
        #pragma unroll
        for (int i = 0; i < 4; i++) {
            int ch = tid + i * 128;
            cpcg16(da + ch * 16, sa + ch * 4);
            cpcg16(db + ch * 16, sb + ch * 4);
        }
        cp_commit();
    }

    __device__ __forceinline__ void run(float c[4][8][4]) {
        stage(0); stage(1); stage(2);
        for (int kc = 0; kc < 16; kc++) {
            if (kc <= 13)      cp_wait<2>();
            else if (kc == 14) cp_wait<1>();
            else               cp_wait<0>();
            __syncthreads();
            const uint32_t* Asl = Ab[kc % 3];
            const uint32_t* Bsl = Bb[kc % 3];
            #pragma unroll
            for (int ks = 0; ks < 2; ks++) {
                uint4 af[4];
                #pragma unroll
                for (int mfl = 0; mfl < 4; mfl++)
                    af[mfl] = *reinterpret_cast<const uint4*>(
                        &Asl[((wm * 4 + mfl) * 2 + ks) * SLOTU + lane * 4]);
                uint4 bf[4];
                #pragma unroll
                for (int np = 0; np < 4; np++)
                    bf[np] = *reinterpret_cast<const uint4*>(
                        &Bsl[((wn * 4 + np) * 2 + ks) * SLOTU + lane * 4]);
                #pragma unroll
                for (int np = 0; np < 4; np++) {
                    #pragma unroll
                    for (int mfl = 0; mfl < 4; mfl++) {
                        const uint32_t* aa = reinterpret_cast<const uint32_t*>(&af[mfl]);
                        mma16h(c[mfl][2 * np + 0], aa, bf[np].x, bf[np].y);
                        mma16h(c[mfl][2 * np + 1], aa, bf[np].z, bf[np].w);
                    }
                }
            }
            __syncthreads();
            if (kc + 3 < 16) stage(kc + 3);
        }
    }
};

// ===========================================================================
// GEMM1/2: C = lrelu(A @ W + bias), output written DIRECTLY as slotted fp16
// A-file for the next stage (C-fragment == A-fragment chaining).
// grid (128 r-tiles, 4 col-blocks), 128 threads.
// ===========================================================================
template <int MODE>   // 0: g_A1 @ Ws1 -> g_A2 ; 1: g_A2 @ Ws2 -> g_A3
__global__ __launch_bounds__(128)
void gemm12_f16(const float* __restrict__ bias)
{
    extern __shared__ uint32_t sm[];
    const int tid  = threadIdx.x;
    const int lane = tid & 31;
    const int wid  = tid >> 5;
    const int g    = lane >> 2;
    const int tig  = lane & 3;
    const int wm   = wid >> 1;
    const int wn   = wid & 1;
    const int tile = blockIdx.x;
    const int col0 = blockIdx.y * 128;

    const uint32_t* srcA = (MODE == 0 ? g_A1 : g_A2) + (size_t)tile * 16 * BUFU;
    const uint32_t* srcB = (MODE == 0 ? g_WB1 : g_WB2) + (size_t)blockIdx.y * 16 * BUFU;
    uint32_t* dstA = (MODE == 0 ? g_A2 : g_A3) + (size_t)tile * 16 * BUFU;

    float c[4][8][4];
    #pragma unroll
    for (int i = 0; i < 4; i++)
        #pragma unroll
        for (int j = 0; j < 8; j++)
            #pragma unroll
            for (int q = 0; q < 4; q++) c[i][j][q] = 0.f;

    Core core{srcA, srcB, {sm, sm + BUFU, sm + 2 * BUFU},
              {sm + 3 * BUFU, sm + 4 * BUFU, sm + 5 * BUFU}, tid, lane, wm, wn};
    core.run(c);

    // --- chaining epilogue: bias + lrelu, pack, store as next-stage A slots ---
    #pragma unroll
    for (int mf = 0; mf < 4; mf++) {
        #pragma unroll
        for (int q = 0; q < 4; q++) {
            const int nf0 = 2 * q, nf1 = 2 * q + 1;
            const int K = col0 + wn * 64 + q * 16 + 2 * tig;
            const float b0 = bias[K],     b1 = bias[K + 1];
            const float b8 = bias[K + 8], b9 = bias[K + 9];
            const int kc_o = (col0 >> 5) + wn * 2 + (q >> 1);
            const int slot = (wm * 4 + mf) * 2 + (q & 1);
            uint4 v;
            v.x = pack_h2(lrelu(c[mf][nf0][0] + b0), lrelu(c[mf][nf0][1] + b1));
            v.y = pack_h2(lrelu(c[mf][nf0][2] + b0), lrelu(c[mf][nf0][3] + b1));
            v.z = pack_h2(lrelu(c[mf][nf1][0] + b8), lrelu(c[mf][nf1][1] + b9));
            v.w = pack_h2(lrelu(c[mf][nf1][2] + b8), lrelu(c[mf][nf1][3] + b9));
            *reinterpret_cast<uint4*>(
                &dstA[(size_t)(kc_o * 16 + slot) * SLOTU + lane * 4]) = v;
        }
    }
}

// ===========================================================================
// GEMM3: fused classifier (R10 core). Tiles consecutive r-rows; epilogue maps
// r -> M = (r&15)*1024 + (r>>4) at the atomicAdd.
// ===========================================================================
__global__ __launch_bounds__(128)
void gemm_head_tc(const float* __restrict__ bc1,
                  const float* __restrict__ Wc2,
                  float* __restrict__ logits)
{
    extern __shared__ uint32_t sm[];
    const int tid  = threadIdx.x;
    const int lane = tid & 31;
    const int wid  = tid >> 5;
    const int g    = lane >> 2;
    const int tig  = lane & 3;
    const int wm   = wid >> 1;
    const int wn   = wid & 1;
    const int tile = blockIdx.x;
    const int hb   = blockIdx.y;
    const int n    = blockIdx.z;
    const int row0 = tile * 128;
    const int h0   = hb * 128;

    const uint32_t* srcA = g_A3 + (size_t)tile * 16 * BUFU;
    const uint32_t* srcB = g_Bh + (size_t)(n * 4 + hb) * 16 * BUFU;

    float c[4][8][4];
    #pragma unroll
    for (int i = 0; i < 4; i++)
        #pragma unroll
        for (int j = 0; j < 8; j++)
            #pragma unroll
            for (int q = 0; q < 4; q++) c[i][j][q] = 0.f;

    Core core{srcA, srcB, {sm, sm + BUFU, sm + 2 * BUFU},
              {sm + 3 * BUFU, sm + 4 * BUFU, sm + 5 * BUFU}, tid, lane, wm, wn};
    core.run(c);

    // --- fused epilogue: lrelu(+bc1)*Wc2, shfl reduce, atomicAdd (M-mapped) ---
    float p[8];
    #pragma unroll
    for (int i = 0; i < 8; i++) p[i] = 0.f;
    #pragma unroll
    for (int nf = 0; nf < 8; nf++) {
        int h = h0 + wn * 64 + nf * 8 + 2 * tig;
        float b1a = bc1[n * HH + h],     b1b = bc1[n * HH + h + 1];
        float w2a = Wc2[n * HH + h],     w2b = Wc2[n * HH + h + 1];
        #pragma unroll
        for (int mf = 0; mf < 4; mf++) {
            p[2 * mf + 0] += lrelu(c[mf][nf][0] + b1a) * w2a
                           + lrelu(c[mf][nf][1] + b1b) * w2b;
            p[2 * mf + 1] += lrelu(c[mf][nf][2] + b1a) * w2a
                           + lrelu(c[mf][nf][3] + b1b) * w2b;
        }
    }
    #pragma unroll
    for (int i = 0; i < 8; i++) {
        float v = p[i];
        v += __shfl_xor_sync(0xffffffffu, v, 1);
        v += __shfl_xor_sync(0xffffffffu, v, 2);
        if (tig == 0) {
            int mf = i >> 1, half = i & 1;
            int r = row0 + wm * 64 + mf * 16 + g + half * 8;
            int M = (r & 15) * 1024 + (r >> 4);
            atomicAdd(&logits[M * NN + n], v);
        }
    }
}

__global__ void zero_kernel(float* __restrict__ p, int n)
{
    int i = blockIdx.x * 256 + threadIdx.x;
    if (i < n) p[i] = 0.f;
}

// full_out += bc2; out[b,n] = sigmoid(diagonal of full_out)
__global__ void finalize_kernel(float* __restrict__ out,
                                const float* __restrict__ bc2)
{
    int idx = blockIdx.x * 256 + threadIdx.x;      // < 262144
    int m = idx >> 4, n = idx & 15;
    float* full = out + MTOT;
    float v = full[idx] + bc2[n];
    full[idx] = v;
    if ((m >> 10) == n) {                           // m = n*1024 + b
        int b = m & 1023;
        out[b * NN + n] = 1.f / (1.f + expf(-v));
    }
}

extern "C" void kernel_launch(void* const* d_in, const int* in_sizes, int n_in,
                              void* d_out, int out_size)
{
    const float* x   = (const float*)d_in[0];
    const float* Ws1 = (const float*)d_in[1];
    const float* bs1 = (const float*)d_in[2];
    const float* Ws2 = (const float*)d_in[3];
    const float* bs2 = (const float*)d_in[4];
    const float* Wc1 = (const float*)d_in[5];
    const float* bc1 = (const float*)d_in[6];
    const float* Wc2 = (const float*)d_in[7];
    const float* bc2 = (const float*)d_in[8];
    float* out = (float*)d_out;

    uint32_t *wb1, *wb2;
    cudaGetSymbolAddress((void**)&wb1, g_WB1);
    cudaGetSymbolAddress((void**)&wb2, g_WB2);

    cudaFuncSetAttribute(gemm12_f16<0>, cudaFuncAttributeMaxDynamicSharedMemorySize, G3_SMEM);
    cudaFuncSetAttribute(gemm12_f16<1>, cudaFuncAttributeMaxDynamicSharedMemorySize, G3_SMEM);
    cudaFuncSetAttribute(gemm_head_tc,  cudaFuncAttributeMaxDynamicSharedMemorySize, G3_SMEM);

    dim3 blk(256);
    // prep: slot-format all GEMM inputs
    prep_xA_kernel<<<4194304 / 256, blk>>>(x);
    prep_wB_kernel<<<131072 / 256, blk>>>(Ws1, wb1);
    prep_wB_kernel<<<131072 / 256, blk>>>(Ws2, wb2);
    prep_slotB_kernel<<<2097152 / 256, blk>>>(Wc1);
    zero_kernel<<<(MTOT * NN + 255) / 256, blk>>>(out + MTOT, MTOT * NN);
    // chained GEMMs (each writes the next stage's slotted A directly)
    gemm12_f16<0><<<dim3(128, 4), dim3(128), G3_SMEM>>>(bs1);
    gemm12_f16<1><<<dim3(128, 4), dim3(128), G3_SMEM>>>(bs2);
    gemm_head_tc<<<dim3(128, 4, NN), dim3(128), G3_SMEM>>>(bc1, Wc2, out + MTOT);
    finalize_kernel<<<(MTOT * NN + 255) / 256, blk>>>(out, bc2);
}